// round 10
// baseline (speedup 1.0000x reference)
#include <cuda_runtime.h>
#include <math.h>
#include <stdint.h>

#define BATCH 4
#define CH 256
#define NSP 4096            // h*w
#define GROUPS 8
#define GELEMS (32*NSP)     // elems per (b,group)
#define EPS 1e-5f

// ---------------- scratch (device globals) ----------------
__device__ float g_xnt [BATCH*NSP*CH];      // groupnorm output, token-major [b][p][c]
__device__ float g_qkvt[BATCH*NSP*3*CH];    // qkv, token-major [b][p][768]
__device__ float g_vt  [BATCH*CH*NSP];      // V [b][c][p]
__device__ float g_S   [(size_t)BATCH*NSP*NSP]; // scores / P   268 MB
__device__ float g_linv[BATCH*NSP];         // 1/rowsum
__device__ float g_attn[BATCH*NSP*CH];      // attention out [b][p][c]
__device__ float g_gnpart[BATCH*GROUPS*8*2];

// ---------------- GroupNorm partial reduction ----------------
__global__ void gn_partial(const float* __restrict__ x) {
    int blk = blockIdx.x;
    int bg = blk >> 3, slice = blk & 7;
    const float4* p4 = (const float4*)(x + bg*GELEMS + slice*(GELEMS/8));
    float s = 0.f, sq = 0.f;
    for (int i = threadIdx.x; i < GELEMS/8/4; i += 256) {
        float4 v = p4[i];
        s  += v.x + v.y + v.z + v.w;
        sq += v.x*v.x + v.y*v.y + v.z*v.z + v.w*v.w;
    }
    __shared__ float ss[256], ssq[256];
    ss[threadIdx.x] = s; ssq[threadIdx.x] = sq;
    __syncthreads();
    for (int st = 128; st > 0; st >>= 1) {
        if (threadIdx.x < st) {
            ss[threadIdx.x]  += ss[threadIdx.x + st];
            ssq[threadIdx.x] += ssq[threadIdx.x + st];
        }
        __syncthreads();
    }
    if (threadIdx.x == 0) {
        g_gnpart[blk*2 + 0] = ss[0];
        g_gnpart[blk*2 + 1] = ssq[0];
    }
}

// ---------------- GroupNorm apply + transpose -> [b][p][c] (64x64 float4) ----------------
__global__ __launch_bounds__(256) void gn_apply_t(const float* __restrict__ x,
                                                  const float* __restrict__ gamma,
                                                  const float* __restrict__ beta) {
    __shared__ float tile[64][65];
    __shared__ float s_ga[64], s_be[64];
    int b = blockIdx.z;
    int p0 = blockIdx.x*64, c0 = blockIdx.y*64;
    int t = threadIdx.x;
    if (t < 64) {
        int c = c0 + t;
        int bg = b*GROUPS + (c >> 5);
        float s = 0.f, sq = 0.f;
#pragma unroll
        for (int k = 0; k < 8; k++) { s += g_gnpart[(bg*8+k)*2]; sq += g_gnpart[(bg*8+k)*2+1]; }
        float mean = s * (1.f/GELEMS);
        float var  = sq * (1.f/GELEMS) - mean*mean;
        float rstd = rsqrtf(var + EPS);
        float ga = gamma[c]*rstd;
        s_ga[t] = ga; s_be[t] = beta[c] - mean*ga;
    }
    __syncthreads();
    const float* X = x + (size_t)b*CH*NSP;
    int cr = t >> 4, p4 = (t & 15)*4;
#pragma unroll
    for (int i = 0; i < 4; i++) {
        int c = cr + i*16;
        float4 v = *(const float4*)&X[(size_t)(c0+c)*NSP + p0 + p4];
        float ga = s_ga[c], be = s_be[c];
        v.x = v.x*ga + be; v.y = v.y*ga + be; v.z = v.z*ga + be; v.w = v.w*ga + be;
        tile[c][p4+0] = v.x; tile[c][p4+1] = v.y; tile[c][p4+2] = v.z; tile[c][p4+3] = v.w;
    }
    __syncthreads();
    float* O = g_xnt + (size_t)b*NSP*CH;
    int pr = t >> 4, c4 = (t & 15)*4;
#pragma unroll
    for (int i = 0; i < 4; i++) {
        int p = pr + i*16;
        float4 o = make_float4(tile[c4+0][p], tile[c4+1][p], tile[c4+2][p], tile[c4+3][p]);
        *(float4*)&O[(size_t)(p0+p)*CH + c0 + c4] = o;
    }
}

// ---------------- V transpose: qkvt [p][768] cols 512..767 -> g_vt [c][p] ----------------
__global__ __launch_bounds__(256) void transposeVt() {
    __shared__ float tile[64][65];
    int b = blockIdx.z;
    int p0 = blockIdx.x*64, c0 = blockIdx.y*64;
    int t = threadIdx.x;
    const float* Q = g_qkvt + (size_t)b*NSP*768;
    int pr = t >> 4, c4 = (t & 15)*4;
#pragma unroll
    for (int i = 0; i < 4; i++) {
        int p = pr + i*16;
        float4 v = *(const float4*)&Q[(size_t)(p0+p)*768 + 512 + c0 + c4];
        tile[c4+0][p] = v.x; tile[c4+1][p] = v.y; tile[c4+2][p] = v.z; tile[c4+3][p] = v.w;
    }
    __syncthreads();
    float* V = g_vt + (size_t)b*CH*NSP;
    int cr = t >> 4, p4 = (t & 15)*4;
#pragma unroll
    for (int i = 0; i < 4; i++) {
        int c = cr + i*16;
        float4 o = make_float4(tile[c][p4+0], tile[c][p4+1], tile[c][p4+2], tile[c][p4+3]);
        *(float4*)&V[(size_t)(c0+c)*NSP + p0 + p4] = o;
    }
}

// ---------------- fast exp on FMA pipe (avoid MUFU bottleneck) ----------------
__device__ __forceinline__ float fast_exp(float x) {
    x = fmaxf(x, -87.0f);
    float y = x * 1.44269504f;
    float t = y + 12582912.0f;            // round-to-nearest via magic number
    int   n = __float_as_int(t) - 0x4B400000;
    float f = y - (t - 12582912.0f);      // f in [-0.5, 0.5]
    float p = 0.00133335581f;
    p = fmaf(p, f, 0.00961812911f);
    p = fmaf(p, f, 0.0555041087f);
    p = fmaf(p, f, 0.240226507f);
    p = fmaf(p, f, 0.693147181f);
    p = fmaf(p, f, 1.0f);
    return __int_as_float(__float_as_int(p) + (n << 23));
}

// ---------------- rowwise softmax (unnormalized; stores 1/sum) ----------------
__global__ __launch_bounds__(256) void softmax_rows() {
    size_t row = blockIdx.x;
    float* S = g_S + row * NSP;
    int t = threadIdx.x;
    float4 v[4];
    float mx = -1e30f;
#pragma unroll
    for (int i = 0; i < 4; i++) {
        v[i] = ((float4*)S)[t + i*256];
        mx = fmaxf(mx, fmaxf(fmaxf(v[i].x, v[i].y), fmaxf(v[i].z, v[i].w)));
    }
#pragma unroll
    for (int o = 16; o > 0; o >>= 1) mx = fmaxf(mx, __shfl_xor_sync(~0u, mx, o));
    __shared__ float sm[8];
    if ((t & 31) == 0) sm[t >> 5] = mx;
    __syncthreads();
#pragma unroll
    for (int i = 0; i < 8; i++) mx = fmaxf(mx, sm[i]);
    const float scale = 0.0625f;   // 1/sqrt(256)
    float sum = 0.f;
#pragma unroll
    for (int i = 0; i < 4; i++) {
        v[i].x = fast_exp((v[i].x - mx)*scale);
        v[i].y = fast_exp((v[i].y - mx)*scale);
        v[i].z = fast_exp((v[i].z - mx)*scale);
        v[i].w = fast_exp((v[i].w - mx)*scale);
        sum += v[i].x + v[i].y + v[i].z + v[i].w;
        ((float4*)S)[t + i*256] = v[i];
    }
#pragma unroll
    for (int o = 16; o > 0; o >>= 1) sum += __shfl_xor_sync(~0u, sum, o);
    __syncthreads();
    if ((t & 31) == 0) sm[t >> 5] = sum;
    __syncthreads();
    if (t == 0) {
        float s = 0.f;
#pragma unroll
        for (int i = 0; i < 8; i++) s += sm[i];
        g_linv[row] = 1.0f / s;
    }
}

// ---------------- tf32 mma.sync GEMM: D[M,N] = A[M,K] x B[N,K]^T ----------------
// BM=128, BN=128, BK=32. 8 warps (2x4), warp tile 64x32, mma m16n8k8.
// 3-stage cp.async pipeline, ONE __syncthreads per k-iteration.
// SMEM tiles K-major, row stride 36 floats => fragment loads hit all 32 banks.
// EPI: 0 = +bias[n]   (qkv)
//      1 = none       (scores)
//      2 = *aux[m]    (PV, 1/l)
//      3 = +bias[m] + res[m][n] (proj)
#define BM 128
#define BN 128
#define BK 32
#define TSTRIDE 36
#define TILEF (128*TSTRIDE)               // floats per tile
#define NSTG 3
#define SMEMSZ (2*NSTG*TILEF*4)           // A0..A2, B0..B2 = 110592 B

#define MMA_TF32(d, a, b) \
    asm volatile("mma.sync.aligned.m16n8k8.row.col.f32.tf32.tf32.f32 " \
        "{%0,%1,%2,%3}, {%4,%5,%6,%7}, {%8,%9}, {%0,%1,%2,%3};" \
        : "+f"((d)[0]), "+f"((d)[1]), "+f"((d)[2]), "+f"((d)[3]) \
        : "r"((a)[0]), "r"((a)[1]), "r"((a)[2]), "r"((a)[3]), \
          "r"((b)[0]), "r"((b)[1]))

template<int EPI>
__global__ __launch_bounds__(256, 2) void mm_tf32(
    const float* __restrict__ Ag, int lda, long sAb,
    const float* __restrict__ Bg, int ldb, long sBb,
    float* __restrict__ Cg, int ldc, long sCb,
    const float* __restrict__ bias,
    const float* __restrict__ auxg, long sXb,
    int K)
{
    extern __shared__ float smf[];
    float* As[NSTG] = { smf,           smf + TILEF,   smf + 2*TILEF };
    float* Bs[NSTG] = { smf + 3*TILEF, smf + 4*TILEF, smf + 5*TILEF };

    int t = threadIdx.x;
    int wid = t >> 5, lane = t & 31;
    int g = lane >> 2, tg = lane & 3;
    int wm = wid >> 2, wn = wid & 3;          // 2 x 4 warp grid
    int n0 = blockIdx.x * BN, m0 = blockIdx.y * BM;
    long b = blockIdx.z;
    const float* A = Ag + b*sAb;
    const float* B = Bg + b*sBb;
    float* C = Cg + b*sCb;

    // cp.async tile loaders: 128 rows x 32 floats, 8 threads per row (16B each)
    int lrow = t >> 3, lc = (t & 7) * 4;
    auto loadAB = [&](int buf, int k0) {
        uint32_t sa = (uint32_t)__cvta_generic_to_shared(As[buf]);
        uint32_t sb = (uint32_t)__cvta_generic_to_shared(Bs[buf]);
#pragma unroll
        for (int i = 0; i < 4; i++) {
            int row = lrow + i*32;
            uint32_t so = sa + (row*TSTRIDE + lc) * 4;
            const float* gp = A + (long)(m0+row)*lda + k0 + lc;
            asm volatile("cp.async.cg.shared.global [%0], [%1], 16;" :: "r"(so), "l"(gp));
        }
#pragma unroll
        for (int i = 0; i < 4; i++) {
            int row = lrow + i*32;
            uint32_t so = sb + (row*TSTRIDE + lc) * 4;
            const float* gp = B + (long)(n0+row)*ldb + k0 + lc;
            asm volatile("cp.async.cg.shared.global [%0], [%1], 16;" :: "r"(so), "l"(gp));
        }
    };

    float acc[4][4][4];
#pragma unroll
    for (int mi = 0; mi < 4; mi++)
#pragma unroll
        for (int nj = 0; nj < 4; nj++)
#pragma unroll
            for (int r = 0; r < 4; r++) acc[mi][nj][r] = 0.f;

    const int NK = K / BK;
    loadAB(0, 0);
    asm volatile("cp.async.commit_group;" ::: "memory");
    loadAB(1, BK);
    asm volatile("cp.async.commit_group;" ::: "memory");

    int cur = 0;
    for (int kt = 0; kt < NK; kt++) {
        asm volatile("cp.async.wait_group 1;" ::: "memory");   // stage kt arrived
        __syncthreads();                                       // visible to all; prev compute done
        if (kt + 2 < NK) {
            int nb = kt + 2 - ((kt+2) >= NSTG ? NSTG : 0);
            nb = (kt + 2) % NSTG;
            loadAB(nb, (kt+2)*BK);
        }
        asm volatile("cp.async.commit_group;" ::: "memory");   // commit (possibly empty)

        const uint32_t* Aw = (const uint32_t*)(As[cur] + (wm*64 + g)*TSTRIDE + tg);
        const uint32_t* Bw = (const uint32_t*)(Bs[cur] + (wn*32 + g)*TSTRIDE + tg);
#pragma unroll
        for (int kk = 0; kk < BK; kk += 8) {
            uint32_t af[4][4], bf[4][2];
#pragma unroll
            for (int mi = 0; mi < 4; mi++) {
                const uint32_t* p = Aw + mi*16*TSTRIDE + kk;
                af[mi][0] = p[0];
                af[mi][1] = p[8*TSTRIDE];
                af[mi][2] = p[4];
                af[mi][3] = p[8*TSTRIDE + 4];
            }
#pragma unroll
            for (int nj = 0; nj < 4; nj++) {
                const uint32_t* p = Bw + nj*8*TSTRIDE + kk;
                bf[nj][0] = p[0];
                bf[nj][1] = p[4];
            }
#pragma unroll
            for (int mi = 0; mi < 4; mi++)
#pragma unroll
                for (int nj = 0; nj < 4; nj++)
                    MMA_TF32(acc[mi][nj], af[mi], bf[nj]);
        }
        cur = (cur + 1 == NSTG) ? 0 : cur + 1;
    }

    // ---- epilogue: acc layout d0:(g, 2tg) d1:(g, 2tg+1) d2:(g+8, 2tg) d3:(g+8, 2tg+1)
    int mb = m0 + wm*64;
    int nb = n0 + wn*32;
#pragma unroll
    for (int mi = 0; mi < 4; mi++) {
        int r0 = mb + mi*16 + g;
        int r1 = r0 + 8;
        float mul0 = 1.f, mul1 = 1.f, add0 = 0.f, add1 = 0.f;
        if (EPI == 2) { mul0 = auxg[b*sXb + r0]; mul1 = auxg[b*sXb + r1]; }
        if (EPI == 3) { add0 = bias[r0];         add1 = bias[r1]; }
#pragma unroll
        for (int nj = 0; nj < 4; nj++) {
            int col = nb + nj*8 + tg*2;
            float2 v0 = make_float2(acc[mi][nj][0], acc[mi][nj][1]);
            float2 v1 = make_float2(acc[mi][nj][2], acc[mi][nj][3]);
            if (EPI == 0) {
                float2 bv = *(const float2*)&bias[col];
                v0.x += bv.x; v0.y += bv.y; v1.x += bv.x; v1.y += bv.y;
            }
            v0.x = v0.x*mul0 + add0; v0.y = v0.y*mul0 + add0;
            v1.x = v1.x*mul1 + add1; v1.y = v1.y*mul1 + add1;
            long o0 = (long)r0*ldc + col;
            long o1 = (long)r1*ldc + col;
            if (EPI == 3) {
                const float* R = auxg + b*sXb;
                float2 x0 = *(const float2*)&R[o0];
                float2 x1 = *(const float2*)&R[o1];
                v0.x += x0.x; v0.y += x0.y; v1.x += x1.x; v1.y += x1.y;
            }
            *(float2*)&C[o0] = v0;
            *(float2*)&C[o1] = v1;
        }
    }
}

// ---------------- launch ----------------
extern "C" void kernel_launch(void* const* d_in, const int* in_sizes, int n_in,
                              void* d_out, int out_size) {
    const float* x      = (const float*)d_in[0];
    const float* gamma  = (const float*)d_in[1];
    const float* beta   = (const float*)d_in[2];
    const float* w_qkv  = (const float*)d_in[3];
    const float* b_qkv  = (const float*)d_in[4];
    const float* w_proj = (const float*)d_in[5];
    const float* b_proj = (const float*)d_in[6];
    float* out = (float*)d_out;

    float *p_xnt, *p_qkvt, *p_vt, *p_S, *p_linv, *p_attn;
    cudaGetSymbolAddress((void**)&p_xnt,  g_xnt);
    cudaGetSymbolAddress((void**)&p_qkvt, g_qkvt);
    cudaGetSymbolAddress((void**)&p_vt,   g_vt);
    cudaGetSymbolAddress((void**)&p_S,    g_S);
    cudaGetSymbolAddress((void**)&p_linv, g_linv);
    cudaGetSymbolAddress((void**)&p_attn, g_attn);

    cudaFuncSetAttribute(mm_tf32<0>, cudaFuncAttributeMaxDynamicSharedMemorySize, SMEMSZ);
    cudaFuncSetAttribute(mm_tf32<1>, cudaFuncAttributeMaxDynamicSharedMemorySize, SMEMSZ);
    cudaFuncSetAttribute(mm_tf32<2>, cudaFuncAttributeMaxDynamicSharedMemorySize, SMEMSZ);
    cudaFuncSetAttribute(mm_tf32<3>, cudaFuncAttributeMaxDynamicSharedMemorySize, SMEMSZ);

    // 1-2. GroupNorm (apply fused with transpose to token-major)
    gn_partial<<<BATCH*GROUPS*8, 256>>>(x);
    gn_apply_t<<<dim3(NSP/64, CH/64, BATCH), 256>>>(x, gamma, beta);

    // 3. QKV: D[p][o] = xnt[p][c] * w_qkv[o][c]^T + b_qkv[o]
    mm_tf32<0><<<dim3(3*CH/BN, NSP/BM, BATCH), 256, SMEMSZ>>>(
        p_xnt, CH, (long)NSP*CH,
        w_qkv, CH, 0,
        p_qkvt, 3*CH, (long)NSP*3*CH,
        b_qkv, nullptr, 0, CH);

    // 4. V -> [c][p]
    transposeVt<<<dim3(NSP/64, CH/64, BATCH), 256>>>();

    // 5. S[i][j] = Q[i][c] * K[j][c]^T   (raw logits; scale folded into softmax)
    mm_tf32<1><<<dim3(NSP/BN, NSP/BM, BATCH), 256, SMEMSZ>>>(
        p_qkvt,       3*CH, (long)NSP*3*CH,
        p_qkvt + CH,  3*CH, (long)NSP*3*CH,
        p_S, NSP, (long)NSP*NSP,
        nullptr, nullptr, 0, CH);

    // 6. softmax rows (unnormalized P, stores 1/l)
    softmax_rows<<<BATCH*NSP, 256>>>();

    // 7. O[i][c] = P[i][j] * Vt[c][j]^T, scaled by 1/l[i]
    mm_tf32<2><<<dim3(CH/BN, NSP/BM, BATCH), 256, SMEMSZ>>>(
        p_S, NSP, (long)NSP*NSP,
        p_vt, NSP, (long)CH*NSP,
        p_attn, CH, (long)NSP*CH,
        nullptr, p_linv, NSP, NSP);

    // 8. out[co][p] = w_proj[co][c] * attn[p][c]^T + b_proj[co] + x
    mm_tf32<3><<<dim3(NSP/BN, CH/BM, BATCH), 256, SMEMSZ>>>(
        w_proj, CH, 0,
        p_attn, CH, (long)NSP*CH,
        out, NSP, (long)CH*NSP,
        b_proj, x, (long)CH*NSP, CH);
}

// round 11
// speedup vs baseline: 1.0888x; 1.0888x over previous
#include <cuda_runtime.h>
#include <math.h>
#include <stdint.h>

#define BATCH 4
#define CH 256
#define NSP 4096            // h*w
#define GROUPS 8
#define GELEMS (32*NSP)     // elems per (b,group)
#define EPS 1e-5f

// ---------------- scratch (device globals) ----------------
__device__ float g_xnt [BATCH*NSP*CH];      // groupnorm output, token-major [b][p][c]
__device__ float g_qkvt[BATCH*NSP*3*CH];    // qkv, token-major [b][p][768]
__device__ float g_vt  [BATCH*CH*NSP];      // V [b][c][p]
__device__ float g_S   [(size_t)BATCH*NSP*NSP]; // exp(scores)   268 MB
__device__ float g_l   [BATCH*NSP];         // rowsum of exp (atomic)
__device__ float g_attn[BATCH*NSP*CH];      // attention out [b][p][c]
__device__ float g_gnpart[BATCH*GROUPS*8*2];

// ---------------- GroupNorm partial reduction ----------------
__global__ void gn_partial(const float* __restrict__ x) {
    int blk = blockIdx.x;
    int bg = blk >> 3, slice = blk & 7;
    const float4* p4 = (const float4*)(x + bg*GELEMS + slice*(GELEMS/8));
    float s = 0.f, sq = 0.f;
    for (int i = threadIdx.x; i < GELEMS/8/4; i += 256) {
        float4 v = p4[i];
        s  += v.x + v.y + v.z + v.w;
        sq += v.x*v.x + v.y*v.y + v.z*v.z + v.w*v.w;
    }
    __shared__ float ss[256], ssq[256];
    ss[threadIdx.x] = s; ssq[threadIdx.x] = sq;
    __syncthreads();
    for (int st = 128; st > 0; st >>= 1) {
        if (threadIdx.x < st) {
            ss[threadIdx.x]  += ss[threadIdx.x + st];
            ssq[threadIdx.x] += ssq[threadIdx.x + st];
        }
        __syncthreads();
    }
    if (threadIdx.x == 0) {
        g_gnpart[blk*2 + 0] = ss[0];
        g_gnpart[blk*2 + 1] = ssq[0];
    }
}

// ---------------- GroupNorm apply + transpose -> [b][p][c] (64x64 float4) ----------------
__global__ __launch_bounds__(256) void gn_apply_t(const float* __restrict__ x,
                                                  const float* __restrict__ gamma,
                                                  const float* __restrict__ beta) {
    __shared__ float tile[64][65];
    __shared__ float s_ga[64], s_be[64];
    int b = blockIdx.z;
    int p0 = blockIdx.x*64, c0 = blockIdx.y*64;
    int t = threadIdx.x;
    if (t < 64) {
        int c = c0 + t;
        int bg = b*GROUPS + (c >> 5);
        float s = 0.f, sq = 0.f;
#pragma unroll
        for (int k = 0; k < 8; k++) { s += g_gnpart[(bg*8+k)*2]; sq += g_gnpart[(bg*8+k)*2+1]; }
        float mean = s * (1.f/GELEMS);
        float var  = sq * (1.f/GELEMS) - mean*mean;
        float rstd = rsqrtf(var + EPS);
        float ga = gamma[c]*rstd;
        s_ga[t] = ga; s_be[t] = beta[c] - mean*ga;
    }
    __syncthreads();
    const float* X = x + (size_t)b*CH*NSP;
    int cr = t >> 4, p4 = (t & 15)*4;
#pragma unroll
    for (int i = 0; i < 4; i++) {
        int c = cr + i*16;
        float4 v = *(const float4*)&X[(size_t)(c0+c)*NSP + p0 + p4];
        float ga = s_ga[c], be = s_be[c];
        v.x = v.x*ga + be; v.y = v.y*ga + be; v.z = v.z*ga + be; v.w = v.w*ga + be;
        tile[c][p4+0] = v.x; tile[c][p4+1] = v.y; tile[c][p4+2] = v.z; tile[c][p4+3] = v.w;
    }
    __syncthreads();
    float* O = g_xnt + (size_t)b*NSP*CH;
    int pr = t >> 4, c4 = (t & 15)*4;
#pragma unroll
    for (int i = 0; i < 4; i++) {
        int p = pr + i*16;
        float4 o = make_float4(tile[c4+0][p], tile[c4+1][p], tile[c4+2][p], tile[c4+3][p]);
        *(float4*)&O[(size_t)(p0+p)*CH + c0 + c4] = o;
    }
}

// ---------------- V transpose: qkvt [p][768] cols 512..767 -> g_vt [c][p] ----------------
__global__ __launch_bounds__(256) void transposeVt() {
    __shared__ float tile[64][65];
    int b = blockIdx.z;
    int p0 = blockIdx.x*64, c0 = blockIdx.y*64;
    int t = threadIdx.x;
    const float* Q = g_qkvt + (size_t)b*NSP*768;
    int pr = t >> 4, c4 = (t & 15)*4;
#pragma unroll
    for (int i = 0; i < 4; i++) {
        int p = pr + i*16;
        float4 v = *(const float4*)&Q[(size_t)(p0+p)*768 + 512 + c0 + c4];
        tile[c4+0][p] = v.x; tile[c4+1][p] = v.y; tile[c4+2][p] = v.z; tile[c4+3][p] = v.w;
    }
    __syncthreads();
    float* V = g_vt + (size_t)b*CH*NSP;
    int cr = t >> 4, p4 = (t & 15)*4;
#pragma unroll
    for (int i = 0; i < 4; i++) {
        int c = cr + i*16;
        float4 o = make_float4(tile[c][p4+0], tile[c][p4+1], tile[c][p4+2], tile[c][p4+3]);
        *(float4*)&V[(size_t)(c0+c)*NSP + p0 + p4] = o;
    }
}

// ---------------- fast exp on FMA pipe (avoid MUFU bottleneck) ----------------
__device__ __forceinline__ float fast_exp(float x) {
    x = fmaxf(x, -87.0f);
    float y = x * 1.44269504f;
    float t = y + 12582912.0f;            // round-to-nearest via magic number
    int   n = __float_as_int(t) - 0x4B400000;
    float f = y - (t - 12582912.0f);      // f in [-0.5, 0.5]
    float p = 0.00133335581f;
    p = fmaf(p, f, 0.00961812911f);
    p = fmaf(p, f, 0.0555041087f);
    p = fmaf(p, f, 0.240226507f);
    p = fmaf(p, f, 0.693147181f);
    p = fmaf(p, f, 1.0f);
    return __int_as_float(__float_as_int(p) + (n << 23));
}

// ---------------- tf32 mma.sync GEMM: D[M,N] = A[M,K] x B[N,K]^T ----------------
// BM=128, BN=256, BK=32. 8 warps (2x4), warp tile 64x64, mma m16n8k8.
// 3-stage cp.async pipeline. SMEM K-major, row stride 36 => conflict-free frags.
// EPI: 0 = +bias[n]                       (qkv)
//      2 = *(1/aux[m])                    (PV)
//      3 = +bias[m] + res[m][n]           (proj)
//      4 = exp(scale*v) + atomic rowsum   (scores)
#define BM 128
#define BN 256
#define BK 32
#define TSTRIDE 36
#define ATILEF (128*TSTRIDE)
#define BTILEF (256*TSTRIDE)
#define NSTG 3
#define SMEMSZ (NSTG*(ATILEF+BTILEF)*4)    // 165888 B

#define MMA_TF32(d, a, b) \
    asm volatile("mma.sync.aligned.m16n8k8.row.col.f32.tf32.tf32.f32 " \
        "{%0,%1,%2,%3}, {%4,%5,%6,%7}, {%8,%9}, {%0,%1,%2,%3};" \
        : "+f"((d)[0]), "+f"((d)[1]), "+f"((d)[2]), "+f"((d)[3]) \
        : "r"((a)[0]), "r"((a)[1]), "r"((a)[2]), "r"((a)[3]), \
          "r"((b)[0]), "r"((b)[1]))

template<int EPI>
__global__ __launch_bounds__(256, 1) void mm_tf32(
    const float* __restrict__ Ag, int lda, long sAb,
    const float* __restrict__ Bg, int ldb, long sBb,
    float* __restrict__ Cg, int ldc, long sCb,
    const float* __restrict__ bias,
    float* __restrict__ auxg, long sXb,
    int K)
{
    extern __shared__ float smf[];
    float* As[NSTG] = { smf, smf + ATILEF, smf + 2*ATILEF };
    float* Bs[NSTG] = { smf + 3*ATILEF, smf + 3*ATILEF + BTILEF, smf + 3*ATILEF + 2*BTILEF };

    int t = threadIdx.x;
    int wid = t >> 5, lane = t & 31;
    int g = lane >> 2, tg = lane & 3;
    int wm = wid >> 2, wn = wid & 3;          // 2 x 4 warp grid (64x64 tiles)
    int n0 = blockIdx.x * BN, m0 = blockIdx.y * BM;
    long b = blockIdx.z;
    const float* A = Ag + b*sAb;
    const float* B = Bg + b*sBb;
    float* C = Cg + b*sCb;

    // cp.async loaders: rows x 32 floats, 8 threads/row (16B each)
    int lrow = t >> 3, lc = (t & 7) * 4;
    auto loadAB = [&](int buf, int k0) {
        uint32_t sa = (uint32_t)__cvta_generic_to_shared(As[buf]);
        uint32_t sb = (uint32_t)__cvta_generic_to_shared(Bs[buf]);
#pragma unroll
        for (int i = 0; i < 4; i++) {
            int row = lrow + i*32;
            uint32_t so = sa + (row*TSTRIDE + lc) * 4;
            const float* gp = A + (long)(m0+row)*lda + k0 + lc;
            asm volatile("cp.async.cg.shared.global [%0], [%1], 16;" :: "r"(so), "l"(gp));
        }
#pragma unroll
        for (int i = 0; i < 8; i++) {
            int row = lrow + i*32;
            uint32_t so = sb + (row*TSTRIDE + lc) * 4;
            const float* gp = B + (long)(n0+row)*ldb + k0 + lc;
            asm volatile("cp.async.cg.shared.global [%0], [%1], 16;" :: "r"(so), "l"(gp));
        }
    };

    float acc[4][8][4];
#pragma unroll
    for (int mi = 0; mi < 4; mi++)
#pragma unroll
        for (int nj = 0; nj < 8; nj++)
#pragma unroll
            for (int r = 0; r < 4; r++) acc[mi][nj][r] = 0.f;

    const int NK = K / BK;
    loadAB(0, 0);
    asm volatile("cp.async.commit_group;" ::: "memory");
    loadAB(1, BK);
    asm volatile("cp.async.commit_group;" ::: "memory");

    int cur = 0;
    for (int kt = 0; kt < NK; kt++) {
        asm volatile("cp.async.wait_group 1;" ::: "memory");
        __syncthreads();
        if (kt + 2 < NK) loadAB((kt + 2) % NSTG, (kt+2)*BK);
        asm volatile("cp.async.commit_group;" ::: "memory");

        const uint32_t* Aw = (const uint32_t*)(As[cur] + (wm*64 + g)*TSTRIDE + tg);
        const uint32_t* Bw = (const uint32_t*)(Bs[cur] + (wn*64 + g)*TSTRIDE + tg);
#pragma unroll
        for (int kk = 0; kk < BK; kk += 8) {
            uint32_t af[4][4];
#pragma unroll
            for (int mi = 0; mi < 4; mi++) {
                const uint32_t* p = Aw + mi*16*TSTRIDE + kk;
                af[mi][0] = p[0];
                af[mi][1] = p[8*TSTRIDE];
                af[mi][2] = p[4];
                af[mi][3] = p[8*TSTRIDE + 4];
            }
#pragma unroll
            for (int nj = 0; nj < 8; nj++) {
                const uint32_t* p = Bw + nj*8*TSTRIDE + kk;
                uint32_t bf[2];
                bf[0] = p[0];
                bf[1] = p[4];
#pragma unroll
                for (int mi = 0; mi < 4; mi++)
                    MMA_TF32(acc[mi][nj], af[mi], bf);
            }
        }
        cur = (cur + 1 == NSTG) ? 0 : cur + 1;
    }

    // ---- epilogue: acc layout d0:(g, 2tg) d1:(g, 2tg+1) d2:(g+8, 2tg) d3:(g+8, 2tg+1)
    int mb = m0 + wm*64;
    int nb = n0 + wn*64;
    const float escale = 0.0625f;   // 1/sqrt(256)
#pragma unroll
    for (int mi = 0; mi < 4; mi++) {
        int r0 = mb + mi*16 + g;
        int r1 = r0 + 8;
        float mul0 = 1.f, mul1 = 1.f, add0 = 0.f, add1 = 0.f;
        if (EPI == 2) { mul0 = 1.0f/auxg[b*sXb + r0]; mul1 = 1.0f/auxg[b*sXb + r1]; }
        if (EPI == 3) { add0 = bias[r0];              add1 = bias[r1]; }
        float rs0 = 0.f, rs1 = 0.f;
#pragma unroll
        for (int nj = 0; nj < 8; nj++) {
            int col = nb + nj*8 + tg*2;
            float2 v0 = make_float2(acc[mi][nj][0], acc[mi][nj][1]);
            float2 v1 = make_float2(acc[mi][nj][2], acc[mi][nj][3]);
            if (EPI == 0) {
                float2 bv = *(const float2*)&bias[col];
                v0.x += bv.x; v0.y += bv.y; v1.x += bv.x; v1.y += bv.y;
            }
            if (EPI == 4) {
                v0.x = fast_exp(v0.x*escale); v0.y = fast_exp(v0.y*escale);
                v1.x = fast_exp(v1.x*escale); v1.y = fast_exp(v1.y*escale);
                rs0 += v0.x + v0.y; rs1 += v1.x + v1.y;
            } else {
                v0.x = v0.x*mul0 + add0; v0.y = v0.y*mul0 + add0;
                v1.x = v1.x*mul1 + add1; v1.y = v1.y*mul1 + add1;
            }
            long o0 = (long)r0*ldc + col;
            long o1 = (long)r1*ldc + col;
            if (EPI == 3) {
                const float* R = auxg + b*sXb;
                float2 x0 = *(const float2*)&R[o0];
                float2 x1 = *(const float2*)&R[o1];
                v0.x += x0.x; v0.y += x0.y; v1.x += x1.x; v1.y += x1.y;
            }
            *(float2*)&C[o0] = v0;
            *(float2*)&C[o1] = v1;
        }
        if (EPI == 4) {
            // reduce over the 4 tg lanes of the quad, one atomic per row
            rs0 += __shfl_xor_sync(~0u, rs0, 1);
            rs0 += __shfl_xor_sync(~0u, rs0, 2);
            rs1 += __shfl_xor_sync(~0u, rs1, 1);
            rs1 += __shfl_xor_sync(~0u, rs1, 2);
            if (tg == 0) {
                atomicAdd(&auxg[b*sXb + r0], rs0);
                atomicAdd(&auxg[b*sXb + r1], rs1);
            }
        }
    }
}

// ---------------- launch ----------------
extern "C" void kernel_launch(void* const* d_in, const int* in_sizes, int n_in,
                              void* d_out, int out_size) {
    const float* x      = (const float*)d_in[0];
    const float* gamma  = (const float*)d_in[1];
    const float* beta   = (const float*)d_in[2];
    const float* w_qkv  = (const float*)d_in[3];
    const float* b_qkv  = (const float*)d_in[4];
    const float* w_proj = (const float*)d_in[5];
    const float* b_proj = (const float*)d_in[6];
    float* out = (float*)d_out;

    float *p_xnt, *p_qkvt, *p_vt, *p_S, *p_l, *p_attn;
    cudaGetSymbolAddress((void**)&p_xnt,  g_xnt);
    cudaGetSymbolAddress((void**)&p_qkvt, g_qkvt);
    cudaGetSymbolAddress((void**)&p_vt,   g_vt);
    cudaGetSymbolAddress((void**)&p_S,    g_S);
    cudaGetSymbolAddress((void**)&p_l,    g_l);
    cudaGetSymbolAddress((void**)&p_attn, g_attn);

    cudaFuncSetAttribute(mm_tf32<0>, cudaFuncAttributeMaxDynamicSharedMemorySize, SMEMSZ);
    cudaFuncSetAttribute(mm_tf32<2>, cudaFuncAttributeMaxDynamicSharedMemorySize, SMEMSZ);
    cudaFuncSetAttribute(mm_tf32<3>, cudaFuncAttributeMaxDynamicSharedMemorySize, SMEMSZ);
    cudaFuncSetAttribute(mm_tf32<4>, cudaFuncAttributeMaxDynamicSharedMemorySize, SMEMSZ);

    // 1-2. GroupNorm (apply fused with transpose to token-major)
    gn_partial<<<BATCH*GROUPS*8, 256>>>(x);
    gn_apply_t<<<dim3(NSP/64, CH/64, BATCH), 256>>>(x, gamma, beta);

    // 3. QKV: D[p][o] = xnt[p][c] * w_qkv[o][c]^T + b_qkv[o]
    mm_tf32<0><<<dim3(3*CH/BN, NSP/BM, BATCH), 256, SMEMSZ>>>(
        p_xnt, CH, (long)NSP*CH,
        w_qkv, CH, 0,
        p_qkvt, 3*CH, (long)NSP*3*CH,
        b_qkv, nullptr, 0, CH);

    // 4. V -> [c][p]
    transposeVt<<<dim3(NSP/64, CH/64, BATCH), 256>>>();

    // 5. zero rowsums, then S = exp(scale * Q K^T) with fused atomic rowsum
    cudaMemsetAsync(p_l, 0, BATCH*NSP*sizeof(float));
    mm_tf32<4><<<dim3(NSP/BN, NSP/BM, BATCH), 256, SMEMSZ>>>(
        p_qkvt,       3*CH, (long)NSP*3*CH,
        p_qkvt + CH,  3*CH, (long)NSP*3*CH,
        p_S, NSP, (long)NSP*NSP,
        nullptr, p_l, NSP, CH);

    // 6. O[i][c] = P[i][j] * Vt[c][j]^T, scaled by 1/l[i]
    mm_tf32<2><<<dim3(CH/BN, NSP/BM, BATCH), 256, SMEMSZ>>>(
        p_S, NSP, (long)NSP*NSP,
        p_vt, NSP, (long)CH*NSP,
        p_attn, CH, (long)NSP*CH,
        nullptr, p_l, NSP, NSP);

    // 7. out[co][p] = w_proj[co][c] * attn[p][c]^T + b_proj[co] + x
    mm_tf32<3><<<dim3(NSP/BN, CH/BM, BATCH), 256, SMEMSZ>>>(
        w_proj, CH, 0,
        p_attn, CH, (long)NSP*CH,
        out, NSP, (long)CH*NSP,
        b_proj, (float*)x, (long)CH*NSP, CH);
}

// round 12
// speedup vs baseline: 1.3302x; 1.2217x over previous
#include <cuda_runtime.h>
#include <cuda_bf16.h>
#include <math.h>
#include <stdint.h>

#define BATCH 4
#define CH 256
#define NSP 4096            // h*w
#define GROUPS 8
#define GELEMS (32*NSP)     // elems per (b,group)
#define EPS 1e-5f

// ---------------- scratch (device globals) ----------------
__device__ float g_xnt [BATCH*NSP*CH];           // groupnorm out, token-major [b][p][c]
__device__ float g_qkvt[BATCH*NSP*3*CH];         // qkv, token-major [b][p][768]
__device__ __nv_bfloat16 g_vtb [BATCH*CH*NSP];   // V^T bf16 [b][c][p]
__device__ __nv_bfloat16 g_P   [(size_t)BATCH*NSP*NSP]; // exp(scores) bf16  134 MB
__device__ float g_l   [BATCH*NSP];              // rowsum of exp (atomic)
__device__ __nv_bfloat16 g_attnb[BATCH*NSP*CH];  // attention out bf16 [b][p][c]
__device__ __nv_bfloat16 g_wpb[CH*CH];           // w_proj bf16
__device__ float g_gnpart[BATCH*GROUPS*8*2];

// ---------------- GroupNorm partial reduction ----------------
__global__ void gn_partial(const float* __restrict__ x) {
    int blk = blockIdx.x;
    int bg = blk >> 3, slice = blk & 7;
    const float4* p4 = (const float4*)(x + bg*GELEMS + slice*(GELEMS/8));
    float s = 0.f, sq = 0.f;
    for (int i = threadIdx.x; i < GELEMS/8/4; i += 256) {
        float4 v = p4[i];
        s  += v.x + v.y + v.z + v.w;
        sq += v.x*v.x + v.y*v.y + v.z*v.z + v.w*v.w;
    }
    __shared__ float ss[256], ssq[256];
    ss[threadIdx.x] = s; ssq[threadIdx.x] = sq;
    __syncthreads();
    for (int st = 128; st > 0; st >>= 1) {
        if (threadIdx.x < st) {
            ss[threadIdx.x]  += ss[threadIdx.x + st];
            ssq[threadIdx.x] += ssq[threadIdx.x + st];
        }
        __syncthreads();
    }
    if (threadIdx.x == 0) {
        g_gnpart[blk*2 + 0] = ss[0];
        g_gnpart[blk*2 + 1] = ssq[0];
    }
}

// ---------------- GroupNorm apply + transpose -> [b][p][c] (64x64 float4) ----------------
__global__ __launch_bounds__(256) void gn_apply_t(const float* __restrict__ x,
                                                  const float* __restrict__ gamma,
                                                  const float* __restrict__ beta) {
    __shared__ float tile[64][65];
    __shared__ float s_ga[64], s_be[64];
    int b = blockIdx.z;
    int p0 = blockIdx.x*64, c0 = blockIdx.y*64;
    int t = threadIdx.x;
    if (t < 64) {
        int c = c0 + t;
        int bg = b*GROUPS + (c >> 5);
        float s = 0.f, sq = 0.f;
#pragma unroll
        for (int k = 0; k < 8; k++) { s += g_gnpart[(bg*8+k)*2]; sq += g_gnpart[(bg*8+k)*2+1]; }
        float mean = s * (1.f/GELEMS);
        float var  = sq * (1.f/GELEMS) - mean*mean;
        float rstd = rsqrtf(var + EPS);
        float ga = gamma[c]*rstd;
        s_ga[t] = ga; s_be[t] = beta[c] - mean*ga;
    }
    __syncthreads();
    const float* X = x + (size_t)b*CH*NSP;
    int cr = t >> 4, p4 = (t & 15)*4;
#pragma unroll
    for (int i = 0; i < 4; i++) {
        int c = cr + i*16;
        float4 v = *(const float4*)&X[(size_t)(c0+c)*NSP + p0 + p4];
        float ga = s_ga[c], be = s_be[c];
        v.x = v.x*ga + be; v.y = v.y*ga + be; v.z = v.z*ga + be; v.w = v.w*ga + be;
        tile[c][p4+0] = v.x; tile[c][p4+1] = v.y; tile[c][p4+2] = v.z; tile[c][p4+3] = v.w;
    }
    __syncthreads();
    float* O = g_xnt + (size_t)b*NSP*CH;
    int pr = t >> 4, c4 = (t & 15)*4;
#pragma unroll
    for (int i = 0; i < 4; i++) {
        int p = pr + i*16;
        float4 o = make_float4(tile[c4+0][p], tile[c4+1][p], tile[c4+2][p], tile[c4+3][p]);
        *(float4*)&O[(size_t)(p0+p)*CH + c0 + c4] = o;
    }
}

// ---------------- V transpose: qkvt [p][768] cols 512..767 -> g_vtb [c][p] bf16 ----------------
__global__ __launch_bounds__(256) void transposeVt() {
    __shared__ float tile[64][65];
    int b = blockIdx.z;
    int p0 = blockIdx.x*64, c0 = blockIdx.y*64;
    int t = threadIdx.x;
    const float* Q = g_qkvt + (size_t)b*NSP*768;
    int pr = t >> 4, c4 = (t & 15)*4;
#pragma unroll
    for (int i = 0; i < 4; i++) {
        int p = pr + i*16;
        float4 v = *(const float4*)&Q[(size_t)(p0+p)*768 + 512 + c0 + c4];
        tile[c4+0][p] = v.x; tile[c4+1][p] = v.y; tile[c4+2][p] = v.z; tile[c4+3][p] = v.w;
    }
    __syncthreads();
    __nv_bfloat16* V = g_vtb + (size_t)b*CH*NSP;
    int cr = t >> 4, p4 = (t & 15)*4;
#pragma unroll
    for (int i = 0; i < 4; i++) {
        int c = cr + i*16;
        __nv_bfloat162 lo = __floats2bfloat162_rn(tile[c][p4+0], tile[c][p4+1]);
        __nv_bfloat162 hi = __floats2bfloat162_rn(tile[c][p4+2], tile[c][p4+3]);
        uint2 pk; pk.x = *(uint32_t*)&lo; pk.y = *(uint32_t*)&hi;
        *(uint2*)&V[(size_t)(c0+c)*NSP + p0 + p4] = pk;
    }
}

// ---------------- w_proj -> bf16 ----------------
__global__ void conv_wproj(const float* __restrict__ w) {
    int i = (blockIdx.x*256 + threadIdx.x) * 4;
    float4 v = *(const float4*)&w[i];
    __nv_bfloat162 lo = __floats2bfloat162_rn(v.x, v.y);
    __nv_bfloat162 hi = __floats2bfloat162_rn(v.z, v.w);
    uint2 pk; pk.x = *(uint32_t*)&lo; pk.y = *(uint32_t*)&hi;
    *(uint2*)&g_wpb[i] = pk;
}

// ---------------- fast exp on FMA pipe ----------------
__device__ __forceinline__ float fast_exp(float x) {
    x = fmaxf(x, -87.0f);
    float y = x * 1.44269504f;
    float t = y + 12582912.0f;
    int   n = __float_as_int(t) - 0x4B400000;
    float f = y - (t - 12582912.0f);
    float p = 0.00133335581f;
    p = fmaf(p, f, 0.00961812911f);
    p = fmaf(p, f, 0.0555041087f);
    p = fmaf(p, f, 0.240226507f);
    p = fmaf(p, f, 0.693147181f);
    p = fmaf(p, f, 1.0f);
    return __int_as_float(__float_as_int(p) + (n << 23));
}

// ================= tf32 GEMM (QKV + scores) =================
// BM=128, BN=256, BK=32, 8 warps 2x4, warp tile 64x64, m16n8k8.
// EPI: 0 = +bias[n], fp32 out            (qkv)
//      4 = exp(scale*v) -> bf16 out + atomic fp32 rowsum (scores)
#define BM 128
#define BN 256
#define BK 32
#define TSTRIDE 36
#define ATILEF (128*TSTRIDE)
#define BTILEF (256*TSTRIDE)
#define NSTG 3
#define SMEMSZ_T (NSTG*(ATILEF+BTILEF)*4)

#define MMA_TF32(d, a, b) \
    asm volatile("mma.sync.aligned.m16n8k8.row.col.f32.tf32.tf32.f32 " \
        "{%0,%1,%2,%3}, {%4,%5,%6,%7}, {%8,%9}, {%0,%1,%2,%3};" \
        : "+f"((d)[0]), "+f"((d)[1]), "+f"((d)[2]), "+f"((d)[3]) \
        : "r"((a)[0]), "r"((a)[1]), "r"((a)[2]), "r"((a)[3]), \
          "r"((b)[0]), "r"((b)[1]))

template<int EPI>
__global__ __launch_bounds__(256, 1) void mm_tf32(
    const float* __restrict__ Ag, int lda, long sAb,
    const float* __restrict__ Bg, int ldb, long sBb,
    void* __restrict__ Cg, int ldc, long sCb,
    const float* __restrict__ bias,
    float* __restrict__ auxg, long sXb,
    int K)
{
    extern __shared__ float smf[];
    float* As[NSTG] = { smf, smf + ATILEF, smf + 2*ATILEF };
    float* Bs[NSTG] = { smf + 3*ATILEF, smf + 3*ATILEF + BTILEF, smf + 3*ATILEF + 2*BTILEF };

    int t = threadIdx.x;
    int wid = t >> 5, lane = t & 31;
    int g = lane >> 2, tg = lane & 3;
    int wm = wid >> 2, wn = wid & 3;
    int n0 = blockIdx.x * BN, m0 = blockIdx.y * BM;
    long b = blockIdx.z;
    const float* A = Ag + b*sAb;
    const float* B = Bg + b*sBb;

    int lrow = t >> 3, lc = (t & 7) * 4;
    auto loadAB = [&](int buf, int k0) {
        uint32_t sa = (uint32_t)__cvta_generic_to_shared(As[buf]);
        uint32_t sb = (uint32_t)__cvta_generic_to_shared(Bs[buf]);
#pragma unroll
        for (int i = 0; i < 4; i++) {
            int row = lrow + i*32;
            uint32_t so = sa + (row*TSTRIDE + lc) * 4;
            const float* gp = A + (long)(m0+row)*lda + k0 + lc;
            asm volatile("cp.async.cg.shared.global [%0], [%1], 16;" :: "r"(so), "l"(gp));
        }
#pragma unroll
        for (int i = 0; i < 8; i++) {
            int row = lrow + i*32;
            uint32_t so = sb + (row*TSTRIDE + lc) * 4;
            const float* gp = B + (long)(n0+row)*ldb + k0 + lc;
            asm volatile("cp.async.cg.shared.global [%0], [%1], 16;" :: "r"(so), "l"(gp));
        }
    };

    float acc[4][8][4];
#pragma unroll
    for (int mi = 0; mi < 4; mi++)
#pragma unroll
        for (int nj = 0; nj < 8; nj++)
#pragma unroll
            for (int r = 0; r < 4; r++) acc[mi][nj][r] = 0.f;

    const int NK = K / BK;
    loadAB(0, 0);
    asm volatile("cp.async.commit_group;" ::: "memory");
    loadAB(1, BK);
    asm volatile("cp.async.commit_group;" ::: "memory");

    int cur = 0;
    for (int kt = 0; kt < NK; kt++) {
        asm volatile("cp.async.wait_group 1;" ::: "memory");
        __syncthreads();
        if (kt + 2 < NK) loadAB((kt + 2) % NSTG, (kt+2)*BK);
        asm volatile("cp.async.commit_group;" ::: "memory");

        const uint32_t* Aw = (const uint32_t*)(As[cur] + (wm*64 + g)*TSTRIDE + tg);
        const uint32_t* Bw = (const uint32_t*)(Bs[cur] + (wn*64 + g)*TSTRIDE + tg);
#pragma unroll
        for (int kk = 0; kk < BK; kk += 8) {
            uint32_t af[4][4];
#pragma unroll
            for (int mi = 0; mi < 4; mi++) {
                const uint32_t* p = Aw + mi*16*TSTRIDE + kk;
                af[mi][0] = p[0];
                af[mi][1] = p[8*TSTRIDE];
                af[mi][2] = p[4];
                af[mi][3] = p[8*TSTRIDE + 4];
            }
#pragma unroll
            for (int nj = 0; nj < 8; nj++) {
                const uint32_t* p = Bw + nj*8*TSTRIDE + kk;
                uint32_t bf[2];
                bf[0] = p[0];
                bf[1] = p[4];
#pragma unroll
                for (int mi = 0; mi < 4; mi++)
                    MMA_TF32(acc[mi][nj], af[mi], bf);
            }
        }
        cur = (cur + 1 == NSTG) ? 0 : cur + 1;
    }

    // ---- epilogue ----
    int mb = m0 + wm*64;
    int nb = n0 + wn*64;
    const float escale = 0.0625f;
    float* Cf = (float*)Cg;
    __nv_bfloat16* Cb = (__nv_bfloat16*)Cg;
#pragma unroll
    for (int mi = 0; mi < 4; mi++) {
        int r0 = mb + mi*16 + g;
        int r1 = r0 + 8;
        float rs0 = 0.f, rs1 = 0.f;
#pragma unroll
        for (int nj = 0; nj < 8; nj++) {
            int col = nb + nj*8 + tg*2;
            float2 v0 = make_float2(acc[mi][nj][0], acc[mi][nj][1]);
            float2 v1 = make_float2(acc[mi][nj][2], acc[mi][nj][3]);
            long o0 = (long)r0*ldc + col + b*sCb;
            long o1 = (long)r1*ldc + col + b*sCb;
            if (EPI == 0) {
                float2 bv = *(const float2*)&bias[col];
                v0.x += bv.x; v0.y += bv.y; v1.x += bv.x; v1.y += bv.y;
                *(float2*)&Cf[o0] = v0;
                *(float2*)&Cf[o1] = v1;
            }
            if (EPI == 4) {
                v0.x = fast_exp(v0.x*escale); v0.y = fast_exp(v0.y*escale);
                v1.x = fast_exp(v1.x*escale); v1.y = fast_exp(v1.y*escale);
                rs0 += v0.x + v0.y; rs1 += v1.x + v1.y;
                __nv_bfloat162 h0 = __floats2bfloat162_rn(v0.x, v0.y);
                __nv_bfloat162 h1 = __floats2bfloat162_rn(v1.x, v1.y);
                *(__nv_bfloat162*)&Cb[o0] = h0;
                *(__nv_bfloat162*)&Cb[o1] = h1;
            }
        }
        if (EPI == 4) {
            rs0 += __shfl_xor_sync(~0u, rs0, 1);
            rs0 += __shfl_xor_sync(~0u, rs0, 2);
            rs1 += __shfl_xor_sync(~0u, rs1, 1);
            rs1 += __shfl_xor_sync(~0u, rs1, 2);
            if (tg == 0) {
                atomicAdd(&auxg[b*sXb + r0], rs0);
                atomicAdd(&auxg[b*sXb + r1], rs1);
            }
        }
    }
}

// ================= bf16 GEMM (PV + proj) =================
// BM=128, BN=256, BK=32 (bf16), m16n8k16, warp tile 64x64.
// SMEM row stride 40 b16 -> fragment banks (20g+tg) mod 32 all distinct.
// EPI: 2 = *(1/aux[m]), bf16 out          (PV)
//      3 = +bias[m] + res[m][n], fp32 out (proj)
#define BTS 40
#define ATILB (128*BTS)
#define BTILB (256*BTS)
#define SMEMSZ_B (NSTG*(ATILB+BTILB)*2)

#define MMA_BF16(d, a, b) \
    asm volatile("mma.sync.aligned.m16n8k16.row.col.f32.bf16.bf16.f32 " \
        "{%0,%1,%2,%3}, {%4,%5,%6,%7}, {%8,%9}, {%0,%1,%2,%3};" \
        : "+f"((d)[0]), "+f"((d)[1]), "+f"((d)[2]), "+f"((d)[3]) \
        : "r"((a)[0]), "r"((a)[1]), "r"((a)[2]), "r"((a)[3]), \
          "r"((b)[0]), "r"((b)[1]))

template<int EPI>
__global__ __launch_bounds__(256, 1) void mm_bf16(
    const __nv_bfloat16* __restrict__ Ag, int lda, long sAb,
    const __nv_bfloat16* __restrict__ Bg, int ldb, long sBb,
    void* __restrict__ Cg, int ldc, long sCb,
    const float* __restrict__ bias,
    const float* __restrict__ auxg, long sXb,
    int K)
{
    extern __shared__ __nv_bfloat16 smb[];
    __nv_bfloat16* As[NSTG] = { smb, smb + ATILB, smb + 2*ATILB };
    __nv_bfloat16* Bs[NSTG] = { smb + 3*ATILB, smb + 3*ATILB + BTILB, smb + 3*ATILB + 2*BTILB };

    int t = threadIdx.x;
    int wid = t >> 5, lane = t & 31;
    int g = lane >> 2, tg = lane & 3;
    int wm = wid >> 2, wn = wid & 3;
    int n0 = blockIdx.x * BN, m0 = blockIdx.y * BM;
    long b = blockIdx.z;
    const __nv_bfloat16* A = Ag + b*sAb;
    const __nv_bfloat16* B = Bg + b*sBb;

    // loaders: 4 threads/row, 16B (8 b16) each; row has 32 b16
    int lrow = t >> 2, lc = (t & 3) * 8;
    auto loadAB = [&](int buf, int k0) {
        uint32_t sa = (uint32_t)__cvta_generic_to_shared(As[buf]);
        uint32_t sb = (uint32_t)__cvta_generic_to_shared(Bs[buf]);
#pragma unroll
        for (int i = 0; i < 2; i++) {
            int row = lrow + i*64;
            uint32_t so = sa + (row*BTS + lc) * 2;
            const __nv_bfloat16* gp = A + (long)(m0+row)*lda + k0 + lc;
            asm volatile("cp.async.cg.shared.global [%0], [%1], 16;" :: "r"(so), "l"(gp));
        }
#pragma unroll
        for (int i = 0; i < 4; i++) {
            int row = lrow + i*64;
            uint32_t so = sb + (row*BTS + lc) * 2;
            const __nv_bfloat16* gp = B + (long)(n0+row)*ldb + k0 + lc;
            asm volatile("cp.async.cg.shared.global [%0], [%1], 16;" :: "r"(so), "l"(gp));
        }
    };

    float acc[4][8][4];
#pragma unroll
    for (int mi = 0; mi < 4; mi++)
#pragma unroll
        for (int nj = 0; nj < 8; nj++)
#pragma unroll
            for (int r = 0; r < 4; r++) acc[mi][nj][r] = 0.f;

    const int NK = K / BK;
    loadAB(0, 0);
    asm volatile("cp.async.commit_group;" ::: "memory");
    loadAB(1, BK);
    asm volatile("cp.async.commit_group;" ::: "memory");

    int cur = 0;
    for (int kt = 0; kt < NK; kt++) {
        asm volatile("cp.async.wait_group 1;" ::: "memory");
        __syncthreads();
        if (kt + 2 < NK) loadAB((kt + 2) % NSTG, (kt+2)*BK);
        asm volatile("cp.async.commit_group;" ::: "memory");

        const __nv_bfloat16* Aw = As[cur] + (wm*64 + g)*BTS + 2*tg;
        const __nv_bfloat16* Bw = Bs[cur] + (wn*64 + g)*BTS + 2*tg;
#pragma unroll
        for (int kk = 0; kk < BK; kk += 16) {
            uint32_t af[4][4];
#pragma unroll
            for (int mi = 0; mi < 4; mi++) {
                const __nv_bfloat16* p = Aw + mi*16*BTS + kk;
                af[mi][0] = *(const uint32_t*)(p);
                af[mi][1] = *(const uint32_t*)(p + 8*BTS);
                af[mi][2] = *(const uint32_t*)(p + 8);
                af[mi][3] = *(const uint32_t*)(p + 8*BTS + 8);
            }
#pragma unroll
            for (int nj = 0; nj < 8; nj++) {
                const __nv_bfloat16* p = Bw + nj*8*BTS + kk;
                uint32_t bf[2];
                bf[0] = *(const uint32_t*)(p);
                bf[1] = *(const uint32_t*)(p + 8);
#pragma unroll
                for (int mi = 0; mi < 4; mi++)
                    MMA_BF16(acc[mi][nj], af[mi], bf);
            }
        }
        cur = (cur + 1 == NSTG) ? 0 : cur + 1;
    }

    // ---- epilogue ----
    int mb = m0 + wm*64;
    int nb = n0 + wn*64;
    float* Cf = (float*)Cg;
    __nv_bfloat16* Cb = (__nv_bfloat16*)Cg;
#pragma unroll
    for (int mi = 0; mi < 4; mi++) {
        int r0 = mb + mi*16 + g;
        int r1 = r0 + 8;
        float mul0 = 1.f, mul1 = 1.f, add0 = 0.f, add1 = 0.f;
        if (EPI == 2) { mul0 = 1.0f/auxg[b*sXb + r0]; mul1 = 1.0f/auxg[b*sXb + r1]; }
        if (EPI == 3) { add0 = bias[r0];              add1 = bias[r1]; }
#pragma unroll
        for (int nj = 0; nj < 8; nj++) {
            int col = nb + nj*8 + tg*2;
            float2 v0 = make_float2(acc[mi][nj][0], acc[mi][nj][1]);
            float2 v1 = make_float2(acc[mi][nj][2], acc[mi][nj][3]);
            v0.x = v0.x*mul0 + add0; v0.y = v0.y*mul0 + add0;
            v1.x = v1.x*mul1 + add1; v1.y = v1.y*mul1 + add1;
            long o0 = (long)r0*ldc + col + b*sCb;
            long o1 = (long)r1*ldc + col + b*sCb;
            if (EPI == 2) {
                __nv_bfloat162 h0 = __floats2bfloat162_rn(v0.x, v0.y);
                __nv_bfloat162 h1 = __floats2bfloat162_rn(v1.x, v1.y);
                *(__nv_bfloat162*)&Cb[o0] = h0;
                *(__nv_bfloat162*)&Cb[o1] = h1;
            }
            if (EPI == 3) {
                const float* R = auxg + b*sXb;
                float2 x0 = *(const float2*)&R[(long)r0*ldc + col];
                float2 x1 = *(const float2*)&R[(long)r1*ldc + col];
                v0.x += x0.x; v0.y += x0.y; v1.x += x1.x; v1.y += x1.y;
                *(float2*)&Cf[o0] = v0;
                *(float2*)&Cf[o1] = v1;
            }
        }
    }
}

// ---------------- launch ----------------
extern "C" void kernel_launch(void* const* d_in, const int* in_sizes, int n_in,
                              void* d_out, int out_size) {
    const float* x      = (const float*)d_in[0];
    const float* gamma  = (const float*)d_in[1];
    const float* beta   = (const float*)d_in[2];
    const float* w_qkv  = (const float*)d_in[3];
    const float* b_qkv  = (const float*)d_in[4];
    const float* w_proj = (const float*)d_in[5];
    const float* b_proj = (const float*)d_in[6];
    float* out = (float*)d_out;

    float *p_xnt, *p_qkvt, *p_l;
    __nv_bfloat16 *p_vtb, *p_P, *p_attnb, *p_wpb;
    cudaGetSymbolAddress((void**)&p_xnt,   g_xnt);
    cudaGetSymbolAddress((void**)&p_qkvt,  g_qkvt);
    cudaGetSymbolAddress((void**)&p_vtb,   g_vtb);
    cudaGetSymbolAddress((void**)&p_P,     g_P);
    cudaGetSymbolAddress((void**)&p_l,     g_l);
    cudaGetSymbolAddress((void**)&p_attnb, g_attnb);
    cudaGetSymbolAddress((void**)&p_wpb,   g_wpb);

    cudaFuncSetAttribute(mm_tf32<0>, cudaFuncAttributeMaxDynamicSharedMemorySize, SMEMSZ_T);
    cudaFuncSetAttribute(mm_tf32<4>, cudaFuncAttributeMaxDynamicSharedMemorySize, SMEMSZ_T);
    cudaFuncSetAttribute(mm_bf16<2>, cudaFuncAttributeMaxDynamicSharedMemorySize, SMEMSZ_B);
    cudaFuncSetAttribute(mm_bf16<3>, cudaFuncAttributeMaxDynamicSharedMemorySize, SMEMSZ_B);

    // 1-2. GroupNorm (apply fused with transpose to token-major)
    gn_partial<<<BATCH*GROUPS*8, 256>>>(x);
    gn_apply_t<<<dim3(NSP/64, CH/64, BATCH), 256>>>(x, gamma, beta);

    // w_proj -> bf16 (independent)
    conv_wproj<<<CH*CH/4/256, 256>>>(w_proj);

    // 3. QKV: D[p][o] = xnt[p][c] * w_qkv[o][c]^T + b_qkv[o]   (tf32, fp32 out)
    mm_tf32<0><<<dim3(3*CH/BN, NSP/BM, BATCH), 256, SMEMSZ_T>>>(
        p_xnt, CH, (long)NSP*CH,
        w_qkv, CH, 0,
        p_qkvt, 3*CH, (long)NSP*3*CH,
        b_qkv, nullptr, 0, CH);

    // 4. V -> [c][p] bf16
    transposeVt<<<dim3(NSP/64, CH/64, BATCH), 256>>>();

    // 5. zero rowsums; S = exp(scale * Q K^T) -> bf16 P, fused atomic rowsum
    cudaMemsetAsync(p_l, 0, BATCH*NSP*sizeof(float));
    mm_tf32<4><<<dim3(NSP/BN, NSP/BM, BATCH), 256, SMEMSZ_T>>>(
        p_qkvt,       3*CH, (long)NSP*3*CH,
        p_qkvt + CH,  3*CH, (long)NSP*3*CH,
        p_P, NSP, (long)NSP*NSP,
        nullptr, p_l, NSP, CH);

    // 6. O[i][c] = P[i][j] * Vt[c][j]^T * (1/l[i])   (bf16 in, bf16 out)
    mm_bf16<2><<<dim3(CH/BN, NSP/BM, BATCH), 256, SMEMSZ_B>>>(
        p_P, NSP, (long)NSP*NSP,
        p_vtb, NSP, (long)CH*NSP,
        p_attnb, CH, (long)NSP*CH,
        nullptr, p_l, NSP, NSP);

    // 7. out[co][p] = w_proj[co][c] * attn[p][c]^T + b_proj[co] + x   (bf16 in, fp32 out)
    mm_bf16<3><<<dim3(NSP/BN, CH/BM, BATCH), 256, SMEMSZ_B>>>(
        p_wpb, CH, 0,
        p_attnb, CH, (long)NSP*CH,
        out, NSP, (long)CH*NSP,
        b_proj, x, (long)CH*NSP, CH);
}

// round 13
// speedup vs baseline: 1.6400x; 1.2329x over previous
#include <cuda_runtime.h>
#include <cuda_fp16.h>
#include <math.h>
#include <stdint.h>

#define BATCH 4
#define CH 256
#define NSP 4096            // h*w
#define GROUPS 8
#define GELEMS (32*NSP)     // elems per (b,group)
#define EPS 1e-5f

// ---------------- scratch (device globals) ----------------
__device__ __half g_xnt [BATCH*NSP*CH];          // groupnorm out fp16 [b][p][c]
__device__ __half g_qkvt[BATCH*NSP*3*CH];        // qkv fp16 [b][p][768]
__device__ __half g_vt  [BATCH*CH*NSP];          // V^T fp16 [b][c][p]
__device__ __half g_P   [(size_t)BATCH*NSP*NSP]; // exp(scores) fp16  134 MB
__device__ float  g_l   [BATCH*NSP];             // rowsum of exp (atomic)
__device__ __half g_attn[BATCH*NSP*CH];          // attention out fp16 [b][p][c]
__device__ __half g_wq  [3*CH*CH];               // w_qkv fp16
__device__ __half g_wp  [CH*CH];                 // w_proj fp16
__device__ float  g_gnpart[BATCH*GROUPS*8*2];

// ---------------- GroupNorm partial reduction ----------------
__global__ void gn_partial(const float* __restrict__ x) {
    int blk = blockIdx.x;
    int bg = blk >> 3, slice = blk & 7;
    const float4* p4 = (const float4*)(x + bg*GELEMS + slice*(GELEMS/8));
    float s = 0.f, sq = 0.f;
    for (int i = threadIdx.x; i < GELEMS/8/4; i += 256) {
        float4 v = p4[i];
        s  += v.x + v.y + v.z + v.w;
        sq += v.x*v.x + v.y*v.y + v.z*v.z + v.w*v.w;
    }
    __shared__ float ss[256], ssq[256];
    ss[threadIdx.x] = s; ssq[threadIdx.x] = sq;
    __syncthreads();
    for (int st = 128; st > 0; st >>= 1) {
        if (threadIdx.x < st) {
            ss[threadIdx.x]  += ss[threadIdx.x + st];
            ssq[threadIdx.x] += ssq[threadIdx.x + st];
        }
        __syncthreads();
    }
    if (threadIdx.x == 0) {
        g_gnpart[blk*2 + 0] = ss[0];
        g_gnpart[blk*2 + 1] = ssq[0];
    }
}

// ---------------- GroupNorm apply + transpose -> fp16 [b][p][c] ----------------
__global__ __launch_bounds__(256) void gn_apply_t(const float* __restrict__ x,
                                                  const float* __restrict__ gamma,
                                                  const float* __restrict__ beta) {
    __shared__ float tile[64][65];
    __shared__ float s_ga[64], s_be[64];
    int b = blockIdx.z;
    int p0 = blockIdx.x*64, c0 = blockIdx.y*64;
    int t = threadIdx.x;
    if (t < 64) {
        int c = c0 + t;
        int bg = b*GROUPS + (c >> 5);
        float s = 0.f, sq = 0.f;
#pragma unroll
        for (int k = 0; k < 8; k++) { s += g_gnpart[(bg*8+k)*2]; sq += g_gnpart[(bg*8+k)*2+1]; }
        float mean = s * (1.f/GELEMS);
        float var  = sq * (1.f/GELEMS) - mean*mean;
        float rstd = rsqrtf(var + EPS);
        float ga = gamma[c]*rstd;
        s_ga[t] = ga; s_be[t] = beta[c] - mean*ga;
    }
    __syncthreads();
    const float* X = x + (size_t)b*CH*NSP;
    int cr = t >> 4, p4 = (t & 15)*4;
#pragma unroll
    for (int i = 0; i < 4; i++) {
        int c = cr + i*16;
        float4 v = *(const float4*)&X[(size_t)(c0+c)*NSP + p0 + p4];
        float ga = s_ga[c], be = s_be[c];
        v.x = v.x*ga + be; v.y = v.y*ga + be; v.z = v.z*ga + be; v.w = v.w*ga + be;
        tile[c][p4+0] = v.x; tile[c][p4+1] = v.y; tile[c][p4+2] = v.z; tile[c][p4+3] = v.w;
    }
    __syncthreads();
    __half* O = g_xnt + (size_t)b*NSP*CH;
    int pr = t >> 4, c4 = (t & 15)*4;
#pragma unroll
    for (int i = 0; i < 4; i++) {
        int p = pr + i*16;
        __half2 lo = __floats2half2_rn(tile[c4+0][p], tile[c4+1][p]);
        __half2 hi = __floats2half2_rn(tile[c4+2][p], tile[c4+3][p]);
        uint2 pk; pk.x = *(uint32_t*)&lo; pk.y = *(uint32_t*)&hi;
        *(uint2*)&O[(size_t)(p0+p)*CH + c0 + c4] = pk;
    }
}

// ---------------- V transpose: qkvt fp16 [p][768] cols 512..767 -> g_vt fp16 [c][p] ----------------
__global__ __launch_bounds__(256) void transposeVt() {
    __shared__ float tile[64][65];
    int b = blockIdx.z;
    int p0 = blockIdx.x*64, c0 = blockIdx.y*64;
    int t = threadIdx.x;
    const __half* Q = g_qkvt + (size_t)b*NSP*768;
    int pr = t >> 3, cq = (t & 7)*8;
#pragma unroll
    for (int i = 0; i < 2; i++) {
        int p = pr + i*32;
        uint2 pk = *(const uint2*)&Q[(size_t)(p0+p)*768 + 512 + c0 + cq];
        __half2 h0 = *(__half2*)&pk.x, h1 = *(__half2*)&pk.y;
        tile[cq+0][p] = __low2float(h0);  tile[cq+1][p] = __high2float(h0);
        tile[cq+2][p] = __low2float(h1);  tile[cq+3][p] = __high2float(h1);
        uint2 pk2 = *(const uint2*)&Q[(size_t)(p0+p)*768 + 512 + c0 + cq + 4];
        __half2 h2 = *(__half2*)&pk2.x, h3 = *(__half2*)&pk2.y;
        tile[cq+4][p] = __low2float(h2);  tile[cq+5][p] = __high2float(h2);
        tile[cq+6][p] = __low2float(h3);  tile[cq+7][p] = __high2float(h3);
    }
    __syncthreads();
    __half* V = g_vt + (size_t)b*CH*NSP;
    int cr = t >> 3, pq = (t & 7)*8;
#pragma unroll
    for (int i = 0; i < 2; i++) {
        int c = cr + i*32;
        __half2 a = __floats2half2_rn(tile[c][pq+0], tile[c][pq+1]);
        __half2 d = __floats2half2_rn(tile[c][pq+2], tile[c][pq+3]);
        __half2 e = __floats2half2_rn(tile[c][pq+4], tile[c][pq+5]);
        __half2 f = __floats2half2_rn(tile[c][pq+6], tile[c][pq+7]);
        uint4 pk; pk.x = *(uint32_t*)&a; pk.y = *(uint32_t*)&d;
        pk.z = *(uint32_t*)&e; pk.w = *(uint32_t*)&f;
        *(uint4*)&V[(size_t)(c0+c)*NSP + p0 + pq] = pk;
    }
}

// ---------------- fp32 -> fp16 weight conversion ----------------
__global__ void conv_f16(const float* __restrict__ src, __half* __restrict__ dst) {
    int i = (blockIdx.x*256 + threadIdx.x) * 4;
    float4 v = *(const float4*)&src[i];
    __half2 lo = __floats2half2_rn(v.x, v.y);
    __half2 hi = __floats2half2_rn(v.z, v.w);
    uint2 pk; pk.x = *(uint32_t*)&lo; pk.y = *(uint32_t*)&hi;
    *(uint2*)&dst[i] = pk;
}

// ---------------- fast exp on FMA pipe ----------------
__device__ __forceinline__ float fast_exp(float x) {
    x = fmaxf(x, -87.0f);
    float y = x * 1.44269504f;
    float t = y + 12582912.0f;
    int   n = __float_as_int(t) - 0x4B400000;
    float f = y - (t - 12582912.0f);
    float p = 0.00133335581f;
    p = fmaf(p, f, 0.00961812911f);
    p = fmaf(p, f, 0.0555041087f);
    p = fmaf(p, f, 0.240226507f);
    p = fmaf(p, f, 0.693147181f);
    p = fmaf(p, f, 1.0f);
    return __int_as_float(__float_as_int(p) + (n << 23));
}

// ================= fp16 GEMM: D[M,N] = A[M,K] x B[N,K]^T =================
// BM=128, BN=256, BK=32 (halfs), m16n8k16, 8 warps 2x4, warp tile 64x64.
// SMEM row stride 40 halfs -> fragment banks (20g+tg) mod 32 all distinct.
// 3-stage cp.async pipeline.
// EPI: 0 = +bias[n], fp16 out                     (qkv)
//      2 = *(1/aux[m]), fp16 out                  (PV)
//      3 = +bias[m] + res[m][n], fp32 out         (proj)
//      4 = exp(scale*v) fp16 out + atomic rowsum  (scores)
#define BM 128
#define BN 256
#define BK 32
#define BTS 40
#define ATILB (128*BTS)
#define BTILB (256*BTS)
#define NSTG 3
#define SMEMSZ (NSTG*(ATILB+BTILB)*2)    // 92160 B

#define MMA_F16(d, a, b) \
    asm volatile("mma.sync.aligned.m16n8k16.row.col.f32.f16.f16.f32 " \
        "{%0,%1,%2,%3}, {%4,%5,%6,%7}, {%8,%9}, {%0,%1,%2,%3};" \
        : "+f"((d)[0]), "+f"((d)[1]), "+f"((d)[2]), "+f"((d)[3]) \
        : "r"((a)[0]), "r"((a)[1]), "r"((a)[2]), "r"((a)[3]), \
          "r"((b)[0]), "r"((b)[1]))

template<int EPI>
__global__ __launch_bounds__(256, 1) void mm_f16(
    const __half* __restrict__ Ag, int lda, long sAb,
    const __half* __restrict__ Bg, int ldb, long sBb,
    void* __restrict__ Cg, int ldc, long sCb,
    const float* __restrict__ bias,
    float* __restrict__ auxg, long sXb,
    const float* __restrict__ resg, long sRb,
    int K)
{
    extern __shared__ __half smh[];
    __half* As[NSTG] = { smh, smh + ATILB, smh + 2*ATILB };
    __half* Bs[NSTG] = { smh + 3*ATILB, smh + 3*ATILB + BTILB, smh + 3*ATILB + 2*BTILB };

    int t = threadIdx.x;
    int wid = t >> 5, lane = t & 31;
    int g = lane >> 2, tg = lane & 3;
    int wm = wid >> 2, wn = wid & 3;
    int n0 = blockIdx.x * BN, m0 = blockIdx.y * BM;
    long b = blockIdx.z;
    const __half* A = Ag + b*sAb;
    const __half* B = Bg + b*sBb;

    // loaders: 4 threads/row, 16B (8 halfs) each; row has 32 halfs
    int lrow = t >> 2, lc = (t & 3) * 8;
    auto loadAB = [&](int buf, int k0) {
        uint32_t sa = (uint32_t)__cvta_generic_to_shared(As[buf]);
        uint32_t sb = (uint32_t)__cvta_generic_to_shared(Bs[buf]);
#pragma unroll
        for (int i = 0; i < 2; i++) {
            int row = lrow + i*64;
            uint32_t so = sa + (row*BTS + lc) * 2;
            const __half* gp = A + (long)(m0+row)*lda + k0 + lc;
            asm volatile("cp.async.cg.shared.global [%0], [%1], 16;" :: "r"(so), "l"(gp));
        }
#pragma unroll
        for (int i = 0; i < 4; i++) {
            int row = lrow + i*64;
            uint32_t so = sb + (row*BTS + lc) * 2;
            const __half* gp = B + (long)(n0+row)*ldb + k0 + lc;
            asm volatile("cp.async.cg.shared.global [%0], [%1], 16;" :: "r"(so), "l"(gp));
        }
    };

    float acc[4][8][4];
#pragma unroll
    for (int mi = 0; mi < 4; mi++)
#pragma unroll
        for (int nj = 0; nj < 8; nj++)
#pragma unroll
            for (int r = 0; r < 4; r++) acc[mi][nj][r] = 0.f;

    const int NK = K / BK;
    loadAB(0, 0);
    asm volatile("cp.async.commit_group;" ::: "memory");
    loadAB(1, BK);
    asm volatile("cp.async.commit_group;" ::: "memory");

    int cur = 0;
    for (int kt = 0; kt < NK; kt++) {
        asm volatile("cp.async.wait_group 1;" ::: "memory");
        __syncthreads();
        if (kt + 2 < NK) loadAB((kt + 2) % NSTG, (kt+2)*BK);
        asm volatile("cp.async.commit_group;" ::: "memory");

        const __half* Aw = As[cur] + (wm*64 + g)*BTS + 2*tg;
        const __half* Bw = Bs[cur] + (wn*64 + g)*BTS + 2*tg;
#pragma unroll
        for (int kk = 0; kk < BK; kk += 16) {
            uint32_t af[4][4];
#pragma unroll
            for (int mi = 0; mi < 4; mi++) {
                const __half* p = Aw + mi*16*BTS + kk;
                af[mi][0] = *(const uint32_t*)(p);
                af[mi][1] = *(const uint32_t*)(p + 8*BTS);
                af[mi][2] = *(const uint32_t*)(p + 8);
                af[mi][3] = *(const uint32_t*)(p + 8*BTS + 8);
            }
#pragma unroll
            for (int nj = 0; nj < 8; nj++) {
                const __half* p = Bw + nj*8*BTS + kk;
                uint32_t bf[2];
                bf[0] = *(const uint32_t*)(p);
                bf[1] = *(const uint32_t*)(p + 8);
#pragma unroll
                for (int mi = 0; mi < 4; mi++)
                    MMA_F16(acc[mi][nj], af[mi], bf);
            }
        }
        cur = (cur + 1 == NSTG) ? 0 : cur + 1;
    }

    // ---- epilogue: d0:(g, 2tg) d1:(g, 2tg+1) d2:(g+8, 2tg) d3:(g+8, 2tg+1)
    int mb = m0 + wm*64;
    int nb = n0 + wn*64;
    const float escale = 0.0625f;   // 1/sqrt(256)
    float* Cf = (float*)Cg;
    __half* Ch = (__half*)Cg;
#pragma unroll
    for (int mi = 0; mi < 4; mi++) {
        int r0 = mb + mi*16 + g;
        int r1 = r0 + 8;
        float mul0 = 1.f, mul1 = 1.f, add0 = 0.f, add1 = 0.f;
        if (EPI == 2) { mul0 = 1.0f/auxg[b*sXb + r0]; mul1 = 1.0f/auxg[b*sXb + r1]; }
        if (EPI == 3) { add0 = bias[r0];              add1 = bias[r1]; }
        float rs0 = 0.f, rs1 = 0.f;
#pragma unroll
        for (int nj = 0; nj < 8; nj++) {
            int col = nb + nj*8 + tg*2;
            float2 v0 = make_float2(acc[mi][nj][0], acc[mi][nj][1]);
            float2 v1 = make_float2(acc[mi][nj][2], acc[mi][nj][3]);
            long o0 = (long)r0*ldc + col + b*sCb;
            long o1 = (long)r1*ldc + col + b*sCb;
            if (EPI == 0) {
                float2 bv = *(const float2*)&bias[col];
                v0.x += bv.x; v0.y += bv.y; v1.x += bv.x; v1.y += bv.y;
                __half2 h0 = __floats2half2_rn(v0.x, v0.y);
                __half2 h1 = __floats2half2_rn(v1.x, v1.y);
                *(__half2*)&Ch[o0] = h0;
                *(__half2*)&Ch[o1] = h1;
            }
            if (EPI == 2) {
                v0.x *= mul0; v0.y *= mul0; v1.x *= mul1; v1.y *= mul1;
                __half2 h0 = __floats2half2_rn(v0.x, v0.y);
                __half2 h1 = __floats2half2_rn(v1.x, v1.y);
                *(__half2*)&Ch[o0] = h0;
                *(__half2*)&Ch[o1] = h1;
            }
            if (EPI == 3) {
                const float* R = resg + b*sRb;
                float2 x0 = *(const float2*)&R[(long)r0*ldc + col];
                float2 x1 = *(const float2*)&R[(long)r1*ldc + col];
                v0.x += add0 + x0.x; v0.y += add0 + x0.y;
                v1.x += add1 + x1.x; v1.y += add1 + x1.y;
                *(float2*)&Cf[o0] = v0;
                *(float2*)&Cf[o1] = v1;
            }
            if (EPI == 4) {
                v0.x = fast_exp(v0.x*escale); v0.y = fast_exp(v0.y*escale);
                v1.x = fast_exp(v1.x*escale); v1.y = fast_exp(v1.y*escale);
                rs0 += v0.x + v0.y; rs1 += v1.x + v1.y;
                __half2 h0 = __floats2half2_rn(v0.x, v0.y);
                __half2 h1 = __floats2half2_rn(v1.x, v1.y);
                *(__half2*)&Ch[o0] = h0;
                *(__half2*)&Ch[o1] = h1;
            }
        }
        if (EPI == 4) {
            rs0 += __shfl_xor_sync(~0u, rs0, 1);
            rs0 += __shfl_xor_sync(~0u, rs0, 2);
            rs1 += __shfl_xor_sync(~0u, rs1, 1);
            rs1 += __shfl_xor_sync(~0u, rs1, 2);
            if (tg == 0) {
                atomicAdd(&auxg[b*sXb + r0], rs0);
                atomicAdd(&auxg[b*sXb + r1], rs1);
            }
        }
    }
}

// ---------------- launch ----------------
extern "C" void kernel_launch(void* const* d_in, const int* in_sizes, int n_in,
                              void* d_out, int out_size) {
    const float* x      = (const float*)d_in[0];
    const float* gamma  = (const float*)d_in[1];
    const float* beta   = (const float*)d_in[2];
    const float* w_qkv  = (const float*)d_in[3];
    const float* b_qkv  = (const float*)d_in[4];
    const float* w_proj = (const float*)d_in[5];
    const float* b_proj = (const float*)d_in[6];
    float* out = (float*)d_out;

    float *p_l;
    __half *p_xnt, *p_qkvt, *p_vt, *p_P, *p_attn, *p_wq, *p_wp;
    cudaGetSymbolAddress((void**)&p_xnt,  g_xnt);
    cudaGetSymbolAddress((void**)&p_qkvt, g_qkvt);
    cudaGetSymbolAddress((void**)&p_vt,   g_vt);
    cudaGetSymbolAddress((void**)&p_P,    g_P);
    cudaGetSymbolAddress((void**)&p_l,    g_l);
    cudaGetSymbolAddress((void**)&p_attn, g_attn);
    cudaGetSymbolAddress((void**)&p_wq,   g_wq);
    cudaGetSymbolAddress((void**)&p_wp,   g_wp);

    cudaFuncSetAttribute(mm_f16<0>, cudaFuncAttributeMaxDynamicSharedMemorySize, SMEMSZ);
    cudaFuncSetAttribute(mm_f16<2>, cudaFuncAttributeMaxDynamicSharedMemorySize, SMEMSZ);
    cudaFuncSetAttribute(mm_f16<3>, cudaFuncAttributeMaxDynamicSharedMemorySize, SMEMSZ);
    cudaFuncSetAttribute(mm_f16<4>, cudaFuncAttributeMaxDynamicSharedMemorySize, SMEMSZ);

    // 1-2. GroupNorm (apply fused with transpose, fp16 out)
    gn_partial<<<BATCH*GROUPS*8, 256>>>(x);
    gn_apply_t<<<dim3(NSP/64, CH/64, BATCH), 256>>>(x, gamma, beta);

    // weights -> fp16 (independent)
    conv_f16<<<3*CH*CH/4/256, 256>>>(w_qkv, p_wq);
    conv_f16<<<CH*CH/4/256, 256>>>(w_proj, p_wp);

    // 3. QKV: D[p][o] = xnt[p][c] * w_qkv[o][c]^T + b_qkv[o]   (fp16 out)
    mm_f16<0><<<dim3(3*CH/BN, NSP/BM, BATCH), 256, SMEMSZ>>>(
        p_xnt, CH, (long)NSP*CH,
        p_wq, CH, 0,
        p_qkvt, 3*CH, (long)NSP*3*CH,
        b_qkv, nullptr, 0, nullptr, 0, CH);

    // 4. V -> [c][p] fp16
    transposeVt<<<dim3(NSP/64, CH/64, BATCH), 256>>>();

    // 5. zero rowsums; S = exp(scale * Q K^T) -> fp16 P, fused atomic rowsum
    cudaMemsetAsync(p_l, 0, BATCH*NSP*sizeof(float));
    mm_f16<4><<<dim3(NSP/BN, NSP/BM, BATCH), 256, SMEMSZ>>>(
        p_qkvt,       3*CH, (long)NSP*3*CH,
        p_qkvt + CH,  3*CH, (long)NSP*3*CH,
        p_P, NSP, (long)NSP*NSP,
        nullptr, p_l, NSP, nullptr, 0, CH);

    // 6. O[i][c] = P[i][j] * Vt[c][j]^T * (1/l[i])   (fp16 in/out)
    mm_f16<2><<<dim3(CH/BN, NSP/BM, BATCH), 256, SMEMSZ>>>(
        p_P, NSP, (long)NSP*NSP,
        p_vt, NSP, (long)CH*NSP,
        p_attn, CH, (long)NSP*CH,
        nullptr, p_l, NSP, nullptr, 0, NSP);

    // 7. out[co][p] = w_proj[co][c] * attn[p][c]^T + b_proj[co] + x   (fp32 out)
    mm_f16<3><<<dim3(NSP/BN, CH/BM, BATCH), 256, SMEMSZ>>>(
        p_wp, CH, 0,
        p_attn, CH, (long)NSP*CH,
        out, NSP, (long)CH*NSP,
        b_proj, nullptr, 0, x, (long)CH*NSP, CH);
}

// round 14
// speedup vs baseline: 1.7999x; 1.0975x over previous
#include <cuda_runtime.h>
#include <cuda_fp16.h>
#include <math.h>
#include <stdint.h>

#define BATCH 4
#define CH 256
#define NSP 4096            // h*w
#define GROUPS 8
#define GELEMS (32*NSP)     // elems per (b,group)
#define EPS 1e-5f

// ---------------- scratch (device globals) ----------------
__device__ __half g_xnt [BATCH*NSP*CH];          // groupnorm out fp16 [b][p][c]
__device__ __half g_qkvt[BATCH*NSP*3*CH];        // qkv fp16 [b][p][768]
__device__ __half g_vt  [BATCH*CH*NSP];          // V^T fp16 [b][c][p]
__device__ __half g_attn[BATCH*NSP*CH];          // attention out fp16 [b][p][c]
__device__ __half g_wq  [3*CH*CH];               // w_qkv fp16
__device__ __half g_wp  [CH*CH];                 // w_proj fp16
__device__ float  g_gnpart[BATCH*GROUPS*8*2];

// ---------------- GroupNorm partial reduction ----------------
__global__ void gn_partial(const float* __restrict__ x) {
    int blk = blockIdx.x;
    int bg = blk >> 3, slice = blk & 7;
    const float4* p4 = (const float4*)(x + bg*GELEMS + slice*(GELEMS/8));
    float s = 0.f, sq = 0.f;
    for (int i = threadIdx.x; i < GELEMS/8/4; i += 256) {
        float4 v = p4[i];
        s  += v.x + v.y + v.z + v.w;
        sq += v.x*v.x + v.y*v.y + v.z*v.z + v.w*v.w;
    }
    __shared__ float ss[256], ssq[256];
    ss[threadIdx.x] = s; ssq[threadIdx.x] = sq;
    __syncthreads();
    for (int st = 128; st > 0; st >>= 1) {
        if (threadIdx.x < st) {
            ss[threadIdx.x]  += ss[threadIdx.x + st];
            ssq[threadIdx.x] += ssq[threadIdx.x + st];
        }
        __syncthreads();
    }
    if (threadIdx.x == 0) {
        g_gnpart[blk*2 + 0] = ss[0];
        g_gnpart[blk*2 + 1] = ssq[0];
    }
}

// ---------------- GroupNorm apply + transpose -> fp16 [b][p][c] ----------------
__global__ __launch_bounds__(256) void gn_apply_t(const float* __restrict__ x,
                                                  const float* __restrict__ gamma,
                                                  const float* __restrict__ beta) {
    __shared__ float tile[64][65];
    __shared__ float s_ga[64], s_be[64];
    int b = blockIdx.z;
    int p0 = blockIdx.x*64, c0 = blockIdx.y*64;
    int t = threadIdx.x;
    if (t < 64) {
        int c = c0 + t;
        int bg = b*GROUPS + (c >> 5);
        float s = 0.f, sq = 0.f;
#pragma unroll
        for (int k = 0; k < 8; k++) { s += g_gnpart[(bg*8+k)*2]; sq += g_gnpart[(bg*8+k)*2+1]; }
        float mean = s * (1.f/GELEMS);
        float var  = sq * (1.f/GELEMS) - mean*mean;
        float rstd = rsqrtf(var + EPS);
        float ga = gamma[c]*rstd;
        s_ga[t] = ga; s_be[t] = beta[c] - mean*ga;
    }
    __syncthreads();
    const float* X = x + (size_t)b*CH*NSP;
    int cr = t >> 4, p4 = (t & 15)*4;
#pragma unroll
    for (int i = 0; i < 4; i++) {
        int c = cr + i*16;
        float4 v = *(const float4*)&X[(size_t)(c0+c)*NSP + p0 + p4];
        float ga = s_ga[c], be = s_be[c];
        v.x = v.x*ga + be; v.y = v.y*ga + be; v.z = v.z*ga + be; v.w = v.w*ga + be;
        tile[c][p4+0] = v.x; tile[c][p4+1] = v.y; tile[c][p4+2] = v.z; tile[c][p4+3] = v.w;
    }
    __syncthreads();
    __half* O = g_xnt + (size_t)b*NSP*CH;
    int pr = t >> 4, c4 = (t & 15)*4;
#pragma unroll
    for (int i = 0; i < 4; i++) {
        int p = pr + i*16;
        __half2 lo = __floats2half2_rn(tile[c4+0][p], tile[c4+1][p]);
        __half2 hi = __floats2half2_rn(tile[c4+2][p], tile[c4+3][p]);
        uint2 pk; pk.x = *(uint32_t*)&lo; pk.y = *(uint32_t*)&hi;
        *(uint2*)&O[(size_t)(p0+p)*CH + c0 + c4] = pk;
    }
}

// ---------------- V transpose: qkvt fp16 [p][768] cols 512..767 -> g_vt fp16 [c][p] ----------------
__global__ __launch_bounds__(256) void transposeVt() {
    __shared__ float tile[64][65];
    int b = blockIdx.z;
    int p0 = blockIdx.x*64, c0 = blockIdx.y*64;
    int t = threadIdx.x;
    const __half* Q = g_qkvt + (size_t)b*NSP*768;
    int pr = t >> 3, cq = (t & 7)*8;
#pragma unroll
    for (int i = 0; i < 2; i++) {
        int p = pr + i*32;
        uint2 pk = *(const uint2*)&Q[(size_t)(p0+p)*768 + 512 + c0 + cq];
        __half2 h0 = *(__half2*)&pk.x, h1 = *(__half2*)&pk.y;
        tile[cq+0][p] = __low2float(h0);  tile[cq+1][p] = __high2float(h0);
        tile[cq+2][p] = __low2float(h1);  tile[cq+3][p] = __high2float(h1);
        uint2 pk2 = *(const uint2*)&Q[(size_t)(p0+p)*768 + 512 + c0 + cq + 4];
        __half2 h2 = *(__half2*)&pk2.x, h3 = *(__half2*)&pk2.y;
        tile[cq+4][p] = __low2float(h2);  tile[cq+5][p] = __high2float(h2);
        tile[cq+6][p] = __low2float(h3);  tile[cq+7][p] = __high2float(h3);
    }
    __syncthreads();
    __half* V = g_vt + (size_t)b*CH*NSP;
    int cr = t >> 3, pq = (t & 7)*8;
#pragma unroll
    for (int i = 0; i < 2; i++) {
        int c = cr + i*32;
        __half2 a = __floats2half2_rn(tile[c][pq+0], tile[c][pq+1]);
        __half2 d = __floats2half2_rn(tile[c][pq+2], tile[c][pq+3]);
        __half2 e = __floats2half2_rn(tile[c][pq+4], tile[c][pq+5]);
        __half2 f = __floats2half2_rn(tile[c][pq+6], tile[c][pq+7]);
        uint4 pk; pk.x = *(uint32_t*)&a; pk.y = *(uint32_t*)&d;
        pk.z = *(uint32_t*)&e; pk.w = *(uint32_t*)&f;
        *(uint4*)&V[(size_t)(c0+c)*NSP + p0 + pq] = pk;
    }
}

// ---------------- fp32 -> fp16 weight conversion ----------------
__global__ void conv_f16(const float* __restrict__ src, __half* __restrict__ dst) {
    int i = (blockIdx.x*256 + threadIdx.x) * 4;
    float4 v = *(const float4*)&src[i];
    __half2 lo = __floats2half2_rn(v.x, v.y);
    __half2 hi = __floats2half2_rn(v.z, v.w);
    uint2 pk; pk.x = *(uint32_t*)&lo; pk.y = *(uint32_t*)&hi;
    *(uint2*)&dst[i] = pk;
}

// ---------------- fast exp on FMA pipe ----------------
__device__ __forceinline__ float fast_exp(float x) {
    x = fmaxf(x, -87.0f);
    float y = x * 1.44269504f;
    float t = y + 12582912.0f;
    int   n = __float_as_int(t) - 0x4B400000;
    float f = y - (t - 12582912.0f);
    float p = 0.00133335581f;
    p = fmaf(p, f, 0.00961812911f);
    p = fmaf(p, f, 0.0555041087f);
    p = fmaf(p, f, 0.240226507f);
    p = fmaf(p, f, 0.693147181f);
    p = fmaf(p, f, 1.0f);
    return __int_as_float(__float_as_int(p) + (n << 23));
}

#define MMA_F16(d, a, b) \
    asm volatile("mma.sync.aligned.m16n8k16.row.col.f32.f16.f16.f32 " \
        "{%0,%1,%2,%3}, {%4,%5,%6,%7}, {%8,%9}, {%0,%1,%2,%3};" \
        : "+f"((d)[0]), "+f"((d)[1]), "+f"((d)[2]), "+f"((d)[3]) \
        : "r"((a)[0]), "r"((a)[1]), "r"((a)[2]), "r"((a)[3]), \
          "r"((b)[0]), "r"((b)[1]))

#define CPA16(so, gp) \
    asm volatile("cp.async.cg.shared.global [%0], [%1], 16;" :: "r"(so), "l"(gp))
#define CPA_COMMIT() asm volatile("cp.async.commit_group;" ::: "memory")
#define CPA_WAIT1()  asm volatile("cp.async.wait_group 1;" ::: "memory")

// ================= fused flash attention =================
// grid (32 q-tiles, 4 batches), 256 threads. Q tile resident; 32 KV chunks of 128.
// Per chunk: 8 K-tiles (S phase) + 4 V-tiles (PV phase), one continuous cp.async ring.
// No-max softmax: P = exp(scale*s); O accumulates; divide by rowsum l at the end.
#define FSTR 40
#define QCHH (128*FSTR)           // halfs per 32-k Q chunk
#define PCHH (128*FSTR)
#define RSLOTH (256*FSTR)
#define FSMEM ((8*QCHH + 4*PCHH + 3*RSLOTH)*2 + 512 + 16)

__global__ __launch_bounds__(256, 1) void flash_attn() {
    extern __shared__ __half smh[];
    __half* Qs   = smh;                      // 8 chunks x [128][40]
    __half* Ps   = smh + 8*QCHH;             // 4 chunks x [128][40]
    __half* Ring = Ps + 4*PCHH;              // 3 slots x [256][40]
    float*  sl   = (float*)(Ring + 3*RSLOTH);

    int t = threadIdx.x;
    int lane = t & 31, wid = t >> 5;
    int g = lane >> 2, tg = lane & 3;
    int wm = wid >> 2, wn = wid & 3;          // 2 x 4
    int p0 = blockIdx.x * 128;
    long b = blockIdx.y;
    const __half* QK = g_qkvt + b*(long)NSP*768;
    const __half* VT = g_vt   + b*(long)CH*NSP;

    int lrow = t >> 2, lc = (t & 3) * 8;
    uint32_t ringb = (uint32_t)__cvta_generic_to_shared(Ring);

    // ---- resident Q load (8 chunks of 32 k) ----
    {
        uint32_t sq = (uint32_t)__cvta_generic_to_shared(Qs);
#pragma unroll
        for (int c = 0; c < 8; c++)
#pragma unroll
            for (int i = 0; i < 2; i++) {
                int row = lrow + i*64;
                uint32_t so = sq + (c*QCHH + row*FSTR + lc)*2;
                const __half* gp = QK + (long)(p0+row)*768 + c*32 + lc;
                CPA16(so, gp);
            }
        CPA_COMMIT();
    }
    if (t < 128) sl[t] = 0.f;

    // tile issue: j<8 -> K tile (chunk kv, k-step j); j>=8 -> V tile (k-step j-8)
    auto issue = [&](int c, int j, int slot) {
        uint32_t sb = ringb + slot*RSLOTH*2;
        int kv0 = c*128;
        if (j < 8) {
#pragma unroll
            for (int i = 0; i < 2; i++) {
                int row = lrow + i*64;
                uint32_t so = sb + (row*FSTR + lc)*2;
                const __half* gp = QK + (long)(kv0+row)*768 + 256 + j*32 + lc;
                CPA16(so, gp);
            }
        } else {
#pragma unroll
            for (int i = 0; i < 4; i++) {
                int row = lrow + i*64;
                uint32_t so = sb + (row*FSTR + lc)*2;
                const __half* gp = VT + (long)row*NSP + kv0 + (j-8)*32 + lc;
                CPA16(so, gp);
            }
        }
    };

    float oacc[4][8][4];
#pragma unroll
    for (int mi = 0; mi < 4; mi++)
#pragma unroll
        for (int nj = 0; nj < 8; nj++)
#pragma unroll
            for (int r = 0; r < 4; r++) oacc[mi][nj][r] = 0.f;
    float sacc[4][4][4];
#pragma unroll
    for (int mi = 0; mi < 4; mi++)
#pragma unroll
        for (int nj = 0; nj < 4; nj++)
#pragma unroll
            for (int r = 0; r < 4; r++) sacc[mi][nj][r] = 0.f;

    const int NCH = NSP/128;       // 32 chunks
    const int T = NCH*12;
    const float ES = 0.0625f;      // 1/sqrt(256)

    // pipeline prologue: issue tiles 0,1
    issue(0, 0, 0); CPA_COMMIT();
    issue(0, 1, 1); CPA_COMMIT();
    int nc = 0, njx = 2;           // next tile to issue

    for (int gt = 0; gt < T; gt++) {
        int j = gt % 12;
        int slot = gt % 3;
        CPA_WAIT1();
        __syncthreads();
        if (gt + 2 < T) issue(nc, njx, (gt+2) % 3);
        CPA_COMMIT();
        if (++njx == 12) { njx = 0; nc++; }

        if (j < 8) {
            // ---- S step: sacc += Q_chunk_j . K_tile^T ----
            const __half* Aw = Qs + j*QCHH + (wm*64 + g)*FSTR + 2*tg;
            const __half* Bw = Ring + slot*RSLOTH + (wn*32 + g)*FSTR + 2*tg;
#pragma unroll
            for (int kk = 0; kk < 32; kk += 16) {
                uint32_t af[4][4];
#pragma unroll
                for (int mi = 0; mi < 4; mi++) {
                    const __half* p = Aw + mi*16*FSTR + kk;
                    af[mi][0] = *(const uint32_t*)(p);
                    af[mi][1] = *(const uint32_t*)(p + 8*FSTR);
                    af[mi][2] = *(const uint32_t*)(p + 8);
                    af[mi][3] = *(const uint32_t*)(p + 8*FSTR + 8);
                }
#pragma unroll
                for (int nj = 0; nj < 4; nj++) {
                    const __half* p = Bw + nj*8*FSTR + kk;
                    uint32_t bf[2];
                    bf[0] = *(const uint32_t*)(p);
                    bf[1] = *(const uint32_t*)(p + 8);
#pragma unroll
                    for (int mi = 0; mi < 4; mi++)
                        MMA_F16(sacc[mi][nj], af[mi], bf);
                }
            }
            if (j == 7) {
                // ---- exp + P->SMEM + rowsum; reset sacc ----
                __half* Pb = Ps + wn*PCHH;
#pragma unroll
                for (int mi = 0; mi < 4; mi++) {
                    int r0l = wm*64 + mi*16 + g;
                    int r1l = r0l + 8;
                    float rs0 = 0.f, rs1 = 0.f;
#pragma unroll
                    for (int nj = 0; nj < 4; nj++) {
                        int colb = nj*8 + tg*2;
                        float e00 = fast_exp(sacc[mi][nj][0]*ES);
                        float e01 = fast_exp(sacc[mi][nj][1]*ES);
                        float e10 = fast_exp(sacc[mi][nj][2]*ES);
                        float e11 = fast_exp(sacc[mi][nj][3]*ES);
                        rs0 += e00 + e01; rs1 += e10 + e11;
                        *(__half2*)(Pb + r0l*FSTR + colb) = __floats2half2_rn(e00, e01);
                        *(__half2*)(Pb + r1l*FSTR + colb) = __floats2half2_rn(e10, e11);
                        sacc[mi][nj][0] = 0.f; sacc[mi][nj][1] = 0.f;
                        sacc[mi][nj][2] = 0.f; sacc[mi][nj][3] = 0.f;
                    }
                    rs0 += __shfl_xor_sync(~0u, rs0, 1);
                    rs0 += __shfl_xor_sync(~0u, rs0, 2);
                    rs1 += __shfl_xor_sync(~0u, rs1, 1);
                    rs1 += __shfl_xor_sync(~0u, rs1, 2);
                    if (tg == 0) {
                        atomicAdd(&sl[r0l], rs0);
                        atomicAdd(&sl[r1l], rs1);
                    }
                }
            }
        } else {
            // ---- PV step: oacc += P_chunk_kt . V_tile^T ----
            int kt = j - 8;
            const __half* Aw = Ps + kt*PCHH + (wm*64 + g)*FSTR + 2*tg;
            const __half* Bw = Ring + slot*RSLOTH + (wn*64 + g)*FSTR + 2*tg;
#pragma unroll
            for (int kk = 0; kk < 32; kk += 16) {
                uint32_t af[4][4];
#pragma unroll
                for (int mi = 0; mi < 4; mi++) {
                    const __half* p = Aw + mi*16*FSTR + kk;
                    af[mi][0] = *(const uint32_t*)(p);
                    af[mi][1] = *(const uint32_t*)(p + 8*FSTR);
                    af[mi][2] = *(const uint32_t*)(p + 8);
                    af[mi][3] = *(const uint32_t*)(p + 8*FSTR + 8);
                }
#pragma unroll
                for (int nj = 0; nj < 8; nj++) {
                    const __half* p = Bw + nj*8*FSTR + kk;
                    uint32_t bf[2];
                    bf[0] = *(const uint32_t*)(p);
                    bf[1] = *(const uint32_t*)(p + 8);
#pragma unroll
                    for (int mi = 0; mi < 4; mi++)
                        MMA_F16(oacc[mi][nj], af[mi], bf);
                }
            }
        }
    }

    __syncthreads();   // all rowsum atomics done
    __half* O = g_attn + b*(long)NSP*CH;
#pragma unroll
    for (int mi = 0; mi < 4; mi++) {
        int r0l = wm*64 + mi*16 + g;
        int r1l = r0l + 8;
        float inv0 = 1.0f / sl[r0l];
        float inv1 = 1.0f / sl[r1l];
#pragma unroll
        for (int nj = 0; nj < 8; nj++) {
            int ch = wn*64 + nj*8 + tg*2;
            __half2 h0 = __floats2half2_rn(oacc[mi][nj][0]*inv0, oacc[mi][nj][1]*inv0);
            __half2 h1 = __floats2half2_rn(oacc[mi][nj][2]*inv1, oacc[mi][nj][3]*inv1);
            *(__half2*)&O[(long)(p0 + r0l)*CH + ch] = h0;
            *(__half2*)&O[(long)(p0 + r1l)*CH + ch] = h1;
        }
    }
}

// ================= fp16 GEMM (QKV + proj) =================
#define BM 128
#define BN 256
#define BK 32
#define BTS 40
#define ATILB (128*BTS)
#define BTILB (256*BTS)
#define NSTG 3
#define SMEMSZ (NSTG*(ATILB+BTILB)*2)    // 92160 B

template<int EPI>
__global__ __launch_bounds__(256, 1) void mm_f16(
    const __half* __restrict__ Ag, int lda, long sAb,
    const __half* __restrict__ Bg, int ldb, long sBb,
    void* __restrict__ Cg, int ldc, long sCb,
    const float* __restrict__ bias,
    const float* __restrict__ resg, long sRb,
    int K)
{
    extern __shared__ __half smh2[];
    __half* As[NSTG] = { smh2, smh2 + ATILB, smh2 + 2*ATILB };
    __half* Bs[NSTG] = { smh2 + 3*ATILB, smh2 + 3*ATILB + BTILB, smh2 + 3*ATILB + 2*BTILB };

    int t = threadIdx.x;
    int wid = t >> 5, lane = t & 31;
    int g = lane >> 2, tg = lane & 3;
    int wm = wid >> 2, wn = wid & 3;
    int n0 = blockIdx.x * BN, m0 = blockIdx.y * BM;
    long b = blockIdx.z;
    const __half* A = Ag + b*sAb;
    const __half* B = Bg + b*sBb;

    int lrow = t >> 2, lc = (t & 3) * 8;
    auto loadAB = [&](int buf, int k0) {
        uint32_t sa = (uint32_t)__cvta_generic_to_shared(As[buf]);
        uint32_t sb = (uint32_t)__cvta_generic_to_shared(Bs[buf]);
#pragma unroll
        for (int i = 0; i < 2; i++) {
            int row = lrow + i*64;
            uint32_t so = sa + (row*BTS + lc) * 2;
            const __half* gp = A + (long)(m0+row)*lda + k0 + lc;
            CPA16(so, gp);
        }
#pragma unroll
        for (int i = 0; i < 4; i++) {
            int row = lrow + i*64;
            uint32_t so = sb + (row*BTS + lc) * 2;
            const __half* gp = B + (long)(n0+row)*ldb + k0 + lc;
            CPA16(so, gp);
        }
    };

    float acc[4][8][4];
#pragma unroll
    for (int mi = 0; mi < 4; mi++)
#pragma unroll
        for (int nj = 0; nj < 8; nj++)
#pragma unroll
            for (int r = 0; r < 4; r++) acc[mi][nj][r] = 0.f;

    const int NK = K / BK;
    loadAB(0, 0);
    CPA_COMMIT();
    loadAB(1, BK);
    CPA_COMMIT();

    int cur = 0;
    for (int kt = 0; kt < NK; kt++) {
        CPA_WAIT1();
        __syncthreads();
        if (kt + 2 < NK) loadAB((kt + 2) % NSTG, (kt+2)*BK);
        CPA_COMMIT();

        const __half* Aw = As[cur] + (wm*64 + g)*BTS + 2*tg;
        const __half* Bw = Bs[cur] + (wn*64 + g)*BTS + 2*tg;
#pragma unroll
        for (int kk = 0; kk < BK; kk += 16) {
            uint32_t af[4][4];
#pragma unroll
            for (int mi = 0; mi < 4; mi++) {
                const __half* p = Aw + mi*16*BTS + kk;
                af[mi][0] = *(const uint32_t*)(p);
                af[mi][1] = *(const uint32_t*)(p + 8*BTS);
                af[mi][2] = *(const uint32_t*)(p + 8);
                af[mi][3] = *(const uint32_t*)(p + 8*BTS + 8);
            }
#pragma unroll
            for (int nj = 0; nj < 8; nj++) {
                const __half* p = Bw + nj*8*BTS + kk;
                uint32_t bf[2];
                bf[0] = *(const uint32_t*)(p);
                bf[1] = *(const uint32_t*)(p + 8);
#pragma unroll
                for (int mi = 0; mi < 4; mi++)
                    MMA_F16(acc[mi][nj], af[mi], bf);
            }
        }
        cur = (cur + 1 == NSTG) ? 0 : cur + 1;
    }

    int mb = m0 + wm*64;
    int nb = n0 + wn*64;
    float* Cf = (float*)Cg;
    __half* Ch = (__half*)Cg;
#pragma unroll
    for (int mi = 0; mi < 4; mi++) {
        int r0 = mb + mi*16 + g;
        int r1 = r0 + 8;
        float add0 = 0.f, add1 = 0.f;
        if (EPI == 3) { add0 = bias[r0]; add1 = bias[r1]; }
#pragma unroll
        for (int nj = 0; nj < 8; nj++) {
            int col = nb + nj*8 + tg*2;
            float2 v0 = make_float2(acc[mi][nj][0], acc[mi][nj][1]);
            float2 v1 = make_float2(acc[mi][nj][2], acc[mi][nj][3]);
            long o0 = (long)r0*ldc + col + b*sCb;
            long o1 = (long)r1*ldc + col + b*sCb;
            if (EPI == 0) {
                float2 bv = *(const float2*)&bias[col];
                v0.x += bv.x; v0.y += bv.y; v1.x += bv.x; v1.y += bv.y;
                *(__half2*)&Ch[o0] = __floats2half2_rn(v0.x, v0.y);
                *(__half2*)&Ch[o1] = __floats2half2_rn(v1.x, v1.y);
            }
            if (EPI == 3) {
                const float* R = resg + b*sRb;
                float2 x0 = *(const float2*)&R[(long)r0*ldc + col];
                float2 x1 = *(const float2*)&R[(long)r1*ldc + col];
                v0.x += add0 + x0.x; v0.y += add0 + x0.y;
                v1.x += add1 + x1.x; v1.y += add1 + x1.y;
                *(float2*)&Cf[o0] = v0;
                *(float2*)&Cf[o1] = v1;
            }
        }
    }
}

// ---------------- launch ----------------
extern "C" void kernel_launch(void* const* d_in, const int* in_sizes, int n_in,
                              void* d_out, int out_size) {
    const float* x      = (const float*)d_in[0];
    const float* gamma  = (const float*)d_in[1];
    const float* beta   = (const float*)d_in[2];
    const float* w_qkv  = (const float*)d_in[3];
    const float* b_qkv  = (const float*)d_in[4];
    const float* w_proj = (const float*)d_in[5];
    const float* b_proj = (const float*)d_in[6];
    float* out = (float*)d_out;

    __half *p_xnt, *p_qkvt, *p_attn, *p_wq, *p_wp;
    cudaGetSymbolAddress((void**)&p_xnt,  g_xnt);
    cudaGetSymbolAddress((void**)&p_qkvt, g_qkvt);
    cudaGetSymbolAddress((void**)&p_attn, g_attn);
    cudaGetSymbolAddress((void**)&p_wq,   g_wq);
    cudaGetSymbolAddress((void**)&p_wp,   g_wp);

    cudaFuncSetAttribute(mm_f16<0>, cudaFuncAttributeMaxDynamicSharedMemorySize, SMEMSZ);
    cudaFuncSetAttribute(mm_f16<3>, cudaFuncAttributeMaxDynamicSharedMemorySize, SMEMSZ);
    cudaFuncSetAttribute(flash_attn, cudaFuncAttributeMaxDynamicSharedMemorySize, FSMEM);

    // 1-2. GroupNorm (apply fused with transpose, fp16 out)
    gn_partial<<<BATCH*GROUPS*8, 256>>>(x);
    gn_apply_t<<<dim3(NSP/64, CH/64, BATCH), 256>>>(x, gamma, beta);

    // weights -> fp16 (independent)
    conv_f16<<<3*CH*CH/4/256, 256>>>(w_qkv, p_wq);
    conv_f16<<<CH*CH/4/256, 256>>>(w_proj, p_wp);

    // 3. QKV: D[p][o] = xnt[p][c] * w_qkv[o][c]^T + b_qkv[o]   (fp16 out)
    mm_f16<0><<<dim3(3*CH/BN, NSP/BM, BATCH), 256, SMEMSZ>>>(
        p_xnt, CH, (long)NSP*CH,
        p_wq, CH, 0,
        p_qkvt, 3*CH, (long)NSP*3*CH,
        b_qkv, nullptr, 0, CH);

    // 4. V -> [c][p] fp16
    transposeVt<<<dim3(NSP/64, CH/64, BATCH), 256>>>();

    // 5. fused attention: S -> exp -> PV, P in SMEM only
    flash_attn<<<dim3(NSP/128, BATCH), 256, FSMEM>>>();

    // 6. out[co][p] = w_proj[co][c] * attn[p][c]^T + b_proj[co] + x   (fp32 out)
    mm_f16<3><<<dim3(NSP/BN, CH/BM, BATCH), 256, SMEMSZ>>>(
        p_wp, CH, 0,
        p_attn, CH, (long)NSP*CH,
        out, NSP, (long)CH*NSP,
        b_proj, x, (long)CH*NSP, CH);
}

// round 15
// speedup vs baseline: 1.9463x; 1.0813x over previous
#include <cuda_runtime.h>
#include <cuda_fp16.h>
#include <math.h>
#include <stdint.h>

#define BATCH 4
#define CH 256
#define NSP 4096            // h*w
#define GROUPS 8
#define GELEMS (32*NSP)     // elems per (b,group)
#define EPS 1e-5f

// ---------------- scratch (device globals) ----------------
__device__ __half g_xnt [BATCH*NSP*CH];          // groupnorm out fp16 [b][p][c]
__device__ __half g_qkvt[BATCH*NSP*3*CH];        // qkv fp16 [b][p][768]
__device__ __half g_vt  [BATCH*CH*NSP];          // V^T fp16 [b][c][p]
__device__ __half g_attn[BATCH*NSP*CH];          // attention out fp16 [b][p][c]
__device__ __half g_wq  [3*CH*CH];               // w_qkv fp16
__device__ __half g_wp  [CH*CH];                 // w_proj fp16
__device__ float  g_gnpart[BATCH*GROUPS*8*2];

// ---------------- GroupNorm partial reduction ----------------
__global__ void gn_partial(const float* __restrict__ x) {
    int blk = blockIdx.x;
    int bg = blk >> 3, slice = blk & 7;
    const float4* p4 = (const float4*)(x + bg*GELEMS + slice*(GELEMS/8));
    float s = 0.f, sq = 0.f;
    for (int i = threadIdx.x; i < GELEMS/8/4; i += 256) {
        float4 v = p4[i];
        s  += v.x + v.y + v.z + v.w;
        sq += v.x*v.x + v.y*v.y + v.z*v.z + v.w*v.w;
    }
    __shared__ float ss[256], ssq[256];
    ss[threadIdx.x] = s; ssq[threadIdx.x] = sq;
    __syncthreads();
    for (int st = 128; st > 0; st >>= 1) {
        if (threadIdx.x < st) {
            ss[threadIdx.x]  += ss[threadIdx.x + st];
            ssq[threadIdx.x] += ssq[threadIdx.x + st];
        }
        __syncthreads();
    }
    if (threadIdx.x == 0) {
        g_gnpart[blk*2 + 0] = ss[0];
        g_gnpart[blk*2 + 1] = ssq[0];
    }
}

// ---------------- GroupNorm apply + transpose -> fp16 [b][p][c] ----------------
__global__ __launch_bounds__(256) void gn_apply_t(const float* __restrict__ x,
                                                  const float* __restrict__ gamma,
                                                  const float* __restrict__ beta) {
    __shared__ float tile[64][65];
    __shared__ float s_ga[64], s_be[64];
    int b = blockIdx.z;
    int p0 = blockIdx.x*64, c0 = blockIdx.y*64;
    int t = threadIdx.x;
    if (t < 64) {
        int c = c0 + t;
        int bg = b*GROUPS + (c >> 5);
        float s = 0.f, sq = 0.f;
#pragma unroll
        for (int k = 0; k < 8; k++) { s += g_gnpart[(bg*8+k)*2]; sq += g_gnpart[(bg*8+k)*2+1]; }
        float mean = s * (1.f/GELEMS);
        float var  = sq * (1.f/GELEMS) - mean*mean;
        float rstd = rsqrtf(var + EPS);
        float ga = gamma[c]*rstd;
        s_ga[t] = ga; s_be[t] = beta[c] - mean*ga;
    }
    __syncthreads();
    const float* X = x + (size_t)b*CH*NSP;
    int cr = t >> 4, p4 = (t & 15)*4;
#pragma unroll
    for (int i = 0; i < 4; i++) {
        int c = cr + i*16;
        float4 v = *(const float4*)&X[(size_t)(c0+c)*NSP + p0 + p4];
        float ga = s_ga[c], be = s_be[c];
        v.x = v.x*ga + be; v.y = v.y*ga + be; v.z = v.z*ga + be; v.w = v.w*ga + be;
        tile[c][p4+0] = v.x; tile[c][p4+1] = v.y; tile[c][p4+2] = v.z; tile[c][p4+3] = v.w;
    }
    __syncthreads();
    __half* O = g_xnt + (size_t)b*NSP*CH;
    int pr = t >> 4, c4 = (t & 15)*4;
#pragma unroll
    for (int i = 0; i < 4; i++) {
        int p = pr + i*16;
        __half2 lo = __floats2half2_rn(tile[c4+0][p], tile[c4+1][p]);
        __half2 hi = __floats2half2_rn(tile[c4+2][p], tile[c4+3][p]);
        uint2 pk; pk.x = *(uint32_t*)&lo; pk.y = *(uint32_t*)&hi;
        *(uint2*)&O[(size_t)(p0+p)*CH + c0 + c4] = pk;
    }
}

// ---------------- V transpose: qkvt fp16 [p][768] cols 512..767 -> g_vt fp16 [c][p] ----------------
__global__ __launch_bounds__(256) void transposeVt() {
    __shared__ float tile[64][65];
    int b = blockIdx.z;
    int p0 = blockIdx.x*64, c0 = blockIdx.y*64;
    int t = threadIdx.x;
    const __half* Q = g_qkvt + (size_t)b*NSP*768;
    int pr = t >> 3, cq = (t & 7)*8;
#pragma unroll
    for (int i = 0; i < 2; i++) {
        int p = pr + i*32;
        uint2 pk = *(const uint2*)&Q[(size_t)(p0+p)*768 + 512 + c0 + cq];
        __half2 h0 = *(__half2*)&pk.x, h1 = *(__half2*)&pk.y;
        tile[cq+0][p] = __low2float(h0);  tile[cq+1][p] = __high2float(h0);
        tile[cq+2][p] = __low2float(h1);  tile[cq+3][p] = __high2float(h1);
        uint2 pk2 = *(const uint2*)&Q[(size_t)(p0+p)*768 + 512 + c0 + cq + 4];
        __half2 h2 = *(__half2*)&pk2.x, h3 = *(__half2*)&pk2.y;
        tile[cq+4][p] = __low2float(h2);  tile[cq+5][p] = __high2float(h2);
        tile[cq+6][p] = __low2float(h3);  tile[cq+7][p] = __high2float(h3);
    }
    __syncthreads();
    __half* V = g_vt + (size_t)b*CH*NSP;
    int cr = t >> 3, pq = (t & 7)*8;
#pragma unroll
    for (int i = 0; i < 2; i++) {
        int c = cr + i*32;
        __half2 a = __floats2half2_rn(tile[c][pq+0], tile[c][pq+1]);
        __half2 d = __floats2half2_rn(tile[c][pq+2], tile[c][pq+3]);
        __half2 e = __floats2half2_rn(tile[c][pq+4], tile[c][pq+5]);
        __half2 f = __floats2half2_rn(tile[c][pq+6], tile[c][pq+7]);
        uint4 pk; pk.x = *(uint32_t*)&a; pk.y = *(uint32_t*)&d;
        pk.z = *(uint32_t*)&e; pk.w = *(uint32_t*)&f;
        *(uint4*)&V[(size_t)(c0+c)*NSP + p0 + pq] = pk;
    }
}

// ---------------- fp32 -> fp16 weight conversion (both weights, one launch) ----------------
__global__ void conv_f16_all(const float* __restrict__ wq, const float* __restrict__ wp) {
    int i = (blockIdx.x*256 + threadIdx.x) * 4;
    const float* src; __half* dst; int off;
    if (i < 3*CH*CH) { src = wq; dst = g_wq; off = i; }
    else             { src = wp; dst = g_wp; off = i - 3*CH*CH; }
    float4 v = *(const float4*)&src[off];
    __half2 lo = __floats2half2_rn(v.x, v.y);
    __half2 hi = __floats2half2_rn(v.z, v.w);
    uint2 pk; pk.x = *(uint32_t*)&lo; pk.y = *(uint32_t*)&hi;
    *(uint2*)&dst[off] = pk;
}

// ---------------- fast exp on FMA pipe ----------------
__device__ __forceinline__ float fast_exp(float x) {
    x = fmaxf(x, -87.0f);
    float y = x * 1.44269504f;
    float t = y + 12582912.0f;
    int   n = __float_as_int(t) - 0x4B400000;
    float f = y - (t - 12582912.0f);
    float p = 0.00133335581f;
    p = fmaf(p, f, 0.00961812911f);
    p = fmaf(p, f, 0.0555041087f);
    p = fmaf(p, f, 0.240226507f);
    p = fmaf(p, f, 0.693147181f);
    p = fmaf(p, f, 1.0f);
    return __int_as_float(__float_as_int(p) + (n << 23));
}

#define MMA_F16(d, a, b) \
    asm volatile("mma.sync.aligned.m16n8k16.row.col.f32.f16.f16.f32 " \
        "{%0,%1,%2,%3}, {%4,%5,%6,%7}, {%8,%9}, {%0,%1,%2,%3};" \
        : "+f"((d)[0]), "+f"((d)[1]), "+f"((d)[2]), "+f"((d)[3]) \
        : "r"((a)[0]), "r"((a)[1]), "r"((a)[2]), "r"((a)[3]), \
          "r"((b)[0]), "r"((b)[1]))

#define LDSM_X4(r0, r1, r2, r3, addr) \
    asm volatile("ldmatrix.sync.aligned.m8n8.x4.shared.b16 {%0,%1,%2,%3}, [%4];" \
        : "=r"(r0), "=r"(r1), "=r"(r2), "=r"(r3) : "r"(addr))

#define CPA16(so, gp) \
    asm volatile("cp.async.cg.shared.global [%0], [%1], 16;" :: "r"(so), "l"(gp))
#define CPA_COMMIT() asm volatile("cp.async.commit_group;" ::: "memory")
#define CPA_WAIT1()  asm volatile("cp.async.wait_group 1;" ::: "memory")
#define CPA_WAIT2()  asm volatile("cp.async.wait_group 2;" ::: "memory")

// ldmatrix per-lane byte offsets (stride in halfs = STR):
//  A x4: lanes 0-15 -> rows 0-15 col+0; 16-31 -> rows 0-15 col+8
//  B pair-x4: m0/m1 = (nj rows, col+0/+8), m2/m3 = (nj+1 rows, col+0/+8)
#define AOFF(l, STR) ((((l) & 15)*(STR) + (((l) >> 4) << 3)) * 2)
#define BOFF(l, STR) (((((l) & 7) + (((l) >> 4) << 3))*(STR) + ((((l) >> 3) & 1) << 3)) * 2)

// ================= fused flash attention =================
// grid (32 q-tiles, 4 batches), 256 threads. Q tile resident; 32 KV chunks of 128.
// Per chunk: 8 K-tiles (S phase) + 4 V-tiles (PV phase), 4-slot cp.async ring, depth-3 prefetch.
// No-max softmax: P = exp(scale*s); O accumulates; divide by rowsum l at the end.
#define FSTR 40
#define QCHH (128*FSTR)           // halfs per 32-k Q chunk
#define PCHH (128*FSTR)
#define RSLOTH (256*FSTR)
#define NRING 4
#define FSMEM ((8*QCHH + 4*PCHH + NRING*RSLOTH)*2 + 512 + 16)

__global__ __launch_bounds__(256, 1) void flash_attn() {
    extern __shared__ __half smh[];
    __half* Qs   = smh;                      // 8 chunks x [128][40]
    __half* Ps   = smh + 8*QCHH;             // 4 chunks x [128][40]
    __half* Ring = Ps + 4*PCHH;              // NRING slots x [256][40]
    float*  sl   = (float*)(Ring + NRING*RSLOTH);

    int t = threadIdx.x;
    int lane = t & 31, wid = t >> 5;
    int g = lane >> 2, tg = lane & 3;
    int wm = wid >> 2, wn = wid & 3;          // 2 x 4
    int p0 = blockIdx.x * 128;
    long b = blockIdx.y;
    const __half* QK = g_qkvt + b*(long)NSP*768;
    const __half* VT = g_vt   + b*(long)CH*NSP;

    int lrow = t >> 2, lc = (t & 3) * 8;
    uint32_t qsu   = (uint32_t)__cvta_generic_to_shared(Qs);
    uint32_t psu   = (uint32_t)__cvta_generic_to_shared(Ps);
    uint32_t ringu = (uint32_t)__cvta_generic_to_shared(Ring);
    uint32_t aoff = AOFF(lane, FSTR);
    uint32_t boff = BOFF(lane, FSTR);

    // ---- resident Q load (8 chunks of 32 k) ----
#pragma unroll
    for (int c = 0; c < 8; c++)
#pragma unroll
        for (int i = 0; i < 2; i++) {
            int row = lrow + i*64;
            uint32_t so = qsu + (c*QCHH + row*FSTR + lc)*2;
            const __half* gp = QK + (long)(p0+row)*768 + c*32 + lc;
            CPA16(so, gp);
        }
    CPA_COMMIT();
    if (t < 128) sl[t] = 0.f;

    // tile issue: j<8 -> K tile (k-step j); j>=8 -> V tile (k-step j-8)
    auto issue = [&](int c, int j, int slot) {
        uint32_t sb = ringu + slot*RSLOTH*2;
        int kv0 = c*128;
        if (j < 8) {
#pragma unroll
            for (int i = 0; i < 2; i++) {
                int row = lrow + i*64;
                uint32_t so = sb + (row*FSTR + lc)*2;
                const __half* gp = QK + (long)(kv0+row)*768 + 256 + j*32 + lc;
                CPA16(so, gp);
            }
        } else {
#pragma unroll
            for (int i = 0; i < 4; i++) {
                int row = lrow + i*64;
                uint32_t so = sb + (row*FSTR + lc)*2;
                const __half* gp = VT + (long)row*NSP + kv0 + (j-8)*32 + lc;
                CPA16(so, gp);
            }
        }
    };

    float oacc[4][8][4];
#pragma unroll
    for (int mi = 0; mi < 4; mi++)
#pragma unroll
        for (int nj = 0; nj < 8; nj++)
#pragma unroll
            for (int r = 0; r < 4; r++) oacc[mi][nj][r] = 0.f;
    float sacc[4][4][4];
#pragma unroll
    for (int mi = 0; mi < 4; mi++)
#pragma unroll
        for (int nj = 0; nj < 4; nj++)
#pragma unroll
            for (int r = 0; r < 4; r++) sacc[mi][nj][r] = 0.f;

    const int NCH = NSP/128;       // 32 chunks
    const int T = NCH*12;
    const float ES = 0.0625f;      // 1/sqrt(256)

    // prologue: issue tiles 0,1,2 (depth-3 prefetch)
    issue(0, 0, 0); CPA_COMMIT();
    issue(0, 1, 1); CPA_COMMIT();
    issue(0, 2, 2); CPA_COMMIT();
    int nc = 0, njx = 3;           // next tile to issue

    for (int gt = 0; gt < T; gt++) {
        int j = gt % 12;
        int slot = gt % NRING;
        CPA_WAIT2();
        __syncthreads();
        if (gt + 3 < T) issue(nc, njx, (gt+3) % NRING);
        CPA_COMMIT();
        if (++njx == 12) { njx = 0; nc++; }

        if (j < 8) {
            // ---- S step: sacc += Q_chunk_j . K_tile^T ----
            uint32_t Abase = qsu + (j*QCHH + (wm*64)*FSTR)*2 + aoff;
            uint32_t Bbase = ringu + (slot*RSLOTH + (wn*32)*FSTR)*2 + boff;
#pragma unroll
            for (int kk = 0; kk < 32; kk += 16) {
                uint32_t af[4][4];
#pragma unroll
                for (int mi = 0; mi < 4; mi++)
                    LDSM_X4(af[mi][0], af[mi][1], af[mi][2], af[mi][3],
                            Abase + (mi*16*FSTR + kk)*2);
#pragma unroll
                for (int njp = 0; njp < 2; njp++) {
                    uint32_t bfa[2], bfb[2];
                    LDSM_X4(bfa[0], bfa[1], bfb[0], bfb[1],
                            Bbase + (njp*16*FSTR + kk)*2);
#pragma unroll
                    for (int mi = 0; mi < 4; mi++) {
                        MMA_F16(sacc[mi][njp*2+0], af[mi], bfa);
                        MMA_F16(sacc[mi][njp*2+1], af[mi], bfb);
                    }
                }
            }
            if (j == 7) {
                // ---- exp + P->SMEM + rowsum; reset sacc ----
                __half* Pb = Ps + wn*PCHH;
#pragma unroll
                for (int mi = 0; mi < 4; mi++) {
                    int r0l = wm*64 + mi*16 + g;
                    int r1l = r0l + 8;
                    float rs0 = 0.f, rs1 = 0.f;
#pragma unroll
                    for (int nj = 0; nj < 4; nj++) {
                        int colb = nj*8 + tg*2;
                        float e00 = fast_exp(sacc[mi][nj][0]*ES);
                        float e01 = fast_exp(sacc[mi][nj][1]*ES);
                        float e10 = fast_exp(sacc[mi][nj][2]*ES);
                        float e11 = fast_exp(sacc[mi][nj][3]*ES);
                        rs0 += e00 + e01; rs1 += e10 + e11;
                        *(__half2*)(Pb + r0l*FSTR + colb) = __floats2half2_rn(e00, e01);
                        *(__half2*)(Pb + r1l*FSTR + colb) = __floats2half2_rn(e10, e11);
                        sacc[mi][nj][0] = 0.f; sacc[mi][nj][1] = 0.f;
                        sacc[mi][nj][2] = 0.f; sacc[mi][nj][3] = 0.f;
                    }
                    rs0 += __shfl_xor_sync(~0u, rs0, 1);
                    rs0 += __shfl_xor_sync(~0u, rs0, 2);
                    rs1 += __shfl_xor_sync(~0u, rs1, 1);
                    rs1 += __shfl_xor_sync(~0u, rs1, 2);
                    if (tg == 0) {
                        atomicAdd(&sl[r0l], rs0);
                        atomicAdd(&sl[r1l], rs1);
                    }
                }
            }
        } else {
            // ---- PV step: oacc += P_chunk_kt . V_tile^T ----
            int kt = j - 8;
            uint32_t Abase = psu + (kt*PCHH + (wm*64)*FSTR)*2 + aoff;
            uint32_t Bbase = ringu + (slot*RSLOTH + (wn*64)*FSTR)*2 + boff;
#pragma unroll
            for (int kk = 0; kk < 32; kk += 16) {
                uint32_t af[4][4];
#pragma unroll
                for (int mi = 0; mi < 4; mi++)
                    LDSM_X4(af[mi][0], af[mi][1], af[mi][2], af[mi][3],
                            Abase + (mi*16*FSTR + kk)*2);
#pragma unroll
                for (int njp = 0; njp < 4; njp++) {
                    uint32_t bfa[2], bfb[2];
                    LDSM_X4(bfa[0], bfa[1], bfb[0], bfb[1],
                            Bbase + (njp*16*FSTR + kk)*2);
#pragma unroll
                    for (int mi = 0; mi < 4; mi++) {
                        MMA_F16(oacc[mi][njp*2+0], af[mi], bfa);
                        MMA_F16(oacc[mi][njp*2+1], af[mi], bfb);
                    }
                }
            }
        }
    }

    __syncthreads();   // all rowsum atomics done
    __half* O = g_attn + b*(long)NSP*CH;
#pragma unroll
    for (int mi = 0; mi < 4; mi++) {
        int r0l = wm*64 + mi*16 + g;
        int r1l = r0l + 8;
        float inv0 = 1.0f / sl[r0l];
        float inv1 = 1.0f / sl[r1l];
#pragma unroll
        for (int nj = 0; nj < 8; nj++) {
            int ch = wn*64 + nj*8 + tg*2;
            __half2 h0 = __floats2half2_rn(oacc[mi][nj][0]*inv0, oacc[mi][nj][1]*inv0);
            __half2 h1 = __floats2half2_rn(oacc[mi][nj][2]*inv1, oacc[mi][nj][3]*inv1);
            *(__half2*)&O[(long)(p0 + r0l)*CH + ch] = h0;
            *(__half2*)&O[(long)(p0 + r1l)*CH + ch] = h1;
        }
    }
}

// ================= fp16 GEMM (QKV + proj) =================
#define BM 128
#define BN 256
#define BK 32
#define BTS 40
#define ATILB (128*BTS)
#define BTILB (256*BTS)
#define NSTG 3
#define SMEMSZ (NSTG*(ATILB+BTILB)*2)    // 92160 B

template<int EPI>
__global__ __launch_bounds__(256, 1) void mm_f16(
    const __half* __restrict__ Ag, int lda, long sAb,
    const __half* __restrict__ Bg, int ldb, long sBb,
    void* __restrict__ Cg, int ldc, long sCb,
    const float* __restrict__ bias,
    const float* __restrict__ resg, long sRb,
    int K)
{
    extern __shared__ __half smh2[];
    __half* As[NSTG] = { smh2, smh2 + ATILB, smh2 + 2*ATILB };
    __half* Bs[NSTG] = { smh2 + 3*ATILB, smh2 + 3*ATILB + BTILB, smh2 + 3*ATILB + 2*BTILB };

    int t = threadIdx.x;
    int wid = t >> 5, lane = t & 31;
    int g = lane >> 2, tg = lane & 3;
    int wm = wid >> 2, wn = wid & 3;
    int n0 = blockIdx.x * BN, m0 = blockIdx.y * BM;
    long b = blockIdx.z;
    const __half* A = Ag + b*sAb;
    const __half* B = Bg + b*sBb;
    uint32_t aoff = AOFF(lane, BTS);
    uint32_t boff = BOFF(lane, BTS);

    int lrow = t >> 2, lc = (t & 3) * 8;
    auto loadAB = [&](int buf, int k0) {
        uint32_t sa = (uint32_t)__cvta_generic_to_shared(As[buf]);
        uint32_t sb = (uint32_t)__cvta_generic_to_shared(Bs[buf]);
#pragma unroll
        for (int i = 0; i < 2; i++) {
            int row = lrow + i*64;
            uint32_t so = sa + (row*BTS + lc) * 2;
            const __half* gp = A + (long)(m0+row)*lda + k0 + lc;
            CPA16(so, gp);
        }
#pragma unroll
        for (int i = 0; i < 4; i++) {
            int row = lrow + i*64;
            uint32_t so = sb + (row*BTS + lc) * 2;
            const __half* gp = B + (long)(n0+row)*ldb + k0 + lc;
            CPA16(so, gp);
        }
    };

    float acc[4][8][4];
#pragma unroll
    for (int mi = 0; mi < 4; mi++)
#pragma unroll
        for (int nj = 0; nj < 8; nj++)
#pragma unroll
            for (int r = 0; r < 4; r++) acc[mi][nj][r] = 0.f;

    const int NK = K / BK;
    loadAB(0, 0);
    CPA_COMMIT();
    loadAB(1, BK);
    CPA_COMMIT();

    int cur = 0;
    for (int kt = 0; kt < NK; kt++) {
        CPA_WAIT1();
        __syncthreads();
        if (kt + 2 < NK) loadAB((kt + 2) % NSTG, (kt+2)*BK);
        CPA_COMMIT();

        uint32_t Abase = (uint32_t)__cvta_generic_to_shared(As[cur]) + ((wm*64)*BTS)*2 + aoff;
        uint32_t Bbase = (uint32_t)__cvta_generic_to_shared(Bs[cur]) + ((wn*64)*BTS)*2 + boff;
#pragma unroll
        for (int kk = 0; kk < BK; kk += 16) {
            uint32_t af[4][4];
#pragma unroll
            for (int mi = 0; mi < 4; mi++)
                LDSM_X4(af[mi][0], af[mi][1], af[mi][2], af[mi][3],
                        Abase + (mi*16*BTS + kk)*2);
#pragma unroll
            for (int njp = 0; njp < 4; njp++) {
                uint32_t bfa[2], bfb[2];
                LDSM_X4(bfa[0], bfa[1], bfb[0], bfb[1],
                        Bbase + (njp*16*BTS + kk)*2);
#pragma unroll
                for (int mi = 0; mi < 4; mi++) {
                    MMA_F16(acc[mi][njp*2+0], af[mi], bfa);
                    MMA_F16(acc[mi][njp*2+1], af[mi], bfb);
                }
            }
        }
        cur = (cur + 1 == NSTG) ? 0 : cur + 1;
    }

    int mb = m0 + wm*64;
    int nb = n0 + wn*64;
    float* Cf = (float*)Cg;
    __half* Ch = (__half*)Cg;
#pragma unroll
    for (int mi = 0; mi < 4; mi++) {
        int r0 = mb + mi*16 + g;
        int r1 = r0 + 8;
        float add0 = 0.f, add1 = 0.f;
        if (EPI == 3) { add0 = bias[r0]; add1 = bias[r1]; }
#pragma unroll
        for (int nj = 0; nj < 8; nj++) {
            int col = nb + nj*8 + tg*2;
            float2 v0 = make_float2(acc[mi][nj][0], acc[mi][nj][1]);
            float2 v1 = make_float2(acc[mi][nj][2], acc[mi][nj][3]);
            long o0 = (long)r0*ldc + col + b*sCb;
            long o1 = (long)r1*ldc + col + b*sCb;
            if (EPI == 0) {
                float2 bv = *(const float2*)&bias[col];
                v0.x += bv.x; v0.y += bv.y; v1.x += bv.x; v1.y += bv.y;
                *(__half2*)&Ch[o0] = __floats2half2_rn(v0.x, v0.y);
                *(__half2*)&Ch[o1] = __floats2half2_rn(v1.x, v1.y);
            }
            if (EPI == 3) {
                const float* R = resg + b*sRb;
                float2 x0 = *(const float2*)&R[(long)r0*ldc + col];
                float2 x1 = *(const float2*)&R[(long)r1*ldc + col];
                v0.x += add0 + x0.x; v0.y += add0 + x0.y;
                v1.x += add1 + x1.x; v1.y += add1 + x1.y;
                *(float2*)&Cf[o0] = v0;
                *(float2*)&Cf[o1] = v1;
            }
        }
    }
}

// ---------------- launch ----------------
extern "C" void kernel_launch(void* const* d_in, const int* in_sizes, int n_in,
                              void* d_out, int out_size) {
    const float* x      = (const float*)d_in[0];
    const float* gamma  = (const float*)d_in[1];
    const float* beta   = (const float*)d_in[2];
    const float* w_qkv  = (const float*)d_in[3];
    const float* b_qkv  = (const float*)d_in[4];
    const float* w_proj = (const float*)d_in[5];
    const float* b_proj = (const float*)d_in[6];
    float* out = (float*)d_out;

    __half *p_xnt, *p_qkvt, *p_attn, *p_wq, *p_wp;
    cudaGetSymbolAddress((void**)&p_xnt,  g_xnt);
    cudaGetSymbolAddress((void**)&p_qkvt, g_qkvt);
    cudaGetSymbolAddress((void**)&p_attn, g_attn);
    cudaGetSymbolAddress((void**)&p_wq,   g_wq);
    cudaGetSymbolAddress((void**)&p_wp,   g_wp);

    cudaFuncSetAttribute(mm_f16<0>, cudaFuncAttributeMaxDynamicSharedMemorySize, SMEMSZ);
    cudaFuncSetAttribute(mm_f16<3>, cudaFuncAttributeMaxDynamicSharedMemorySize, SMEMSZ);
    cudaFuncSetAttribute(flash_attn, cudaFuncAttributeMaxDynamicSharedMemorySize, FSMEM);

    // 1-2. GroupNorm (apply fused with transpose, fp16 out)
    gn_partial<<<BATCH*GROUPS*8, 256>>>(x);
    gn_apply_t<<<dim3(NSP/64, CH/64, BATCH), 256>>>(x, gamma, beta);

    // weights -> fp16 (one launch)
    conv_f16_all<<<4*CH*CH/4/256, 256>>>(w_qkv, w_proj);

    // 3. QKV: D[p][o] = xnt[p][c] * w_qkv[o][c]^T + b_qkv[o]   (fp16 out)
    mm_f16<0><<<dim3(3*CH/BN, NSP/BM, BATCH), 256, SMEMSZ>>>(
        p_xnt, CH, (long)NSP*CH,
        p_wq, CH, 0,
        p_qkvt, 3*CH, (long)NSP*3*CH,
        b_qkv, nullptr, 0, CH);

    // 4. V -> [c][p] fp16
    transposeVt<<<dim3(NSP/64, CH/64, BATCH), 256>>>();

    // 5. fused attention: S -> exp -> PV, P in SMEM only
    flash_attn<<<dim3(NSP/128, BATCH), 256, FSMEM>>>();

    // 6. out[co][p] = w_proj[co][c] * attn[p][c]^T + b_proj[co] + x   (fp32 out)
    mm_f16<3><<<dim3(NSP/BN, CH/BM, BATCH), 256, SMEMSZ>>>(
        p_wp, CH, 0,
        p_attn, CH, (long)NSP*CH,
        out, NSP, (long)CH*NSP,
        b_proj, x, (long)CH*NSP, CH);
}

// round 16
// speedup vs baseline: 2.1351x; 1.0970x over previous
#include <cuda_runtime.h>
#include <cuda_fp16.h>
#include <math.h>
#include <stdint.h>

#define BATCH 4
#define CH 256
#define NSP 4096            // h*w
#define GROUPS 8
#define GELEMS (32*NSP)     // elems per (b,group)
#define EPS 1e-5f

// ---------------- scratch (device globals) ----------------
__device__ __half g_xnt [BATCH*NSP*CH];          // groupnorm out fp16 [b][p][c]
__device__ __half g_qkvt[BATCH*NSP*2*CH];        // Q,K fp16 [b][p][512]
__device__ __half g_vt  [BATCH*CH*NSP];          // V^T fp16 [b][c][p]
__device__ __half g_attn[BATCH*NSP*CH];          // attention out fp16 [b][p][c]
__device__ __half g_wq  [3*CH*CH];               // w_qkv fp16
__device__ __half g_wp  [CH*CH];                 // w_proj fp16
__device__ float  g_gnpart[BATCH*GROUPS*8*2];

// ---------------- GroupNorm partial reduction ----------------
__global__ void gn_partial(const float* __restrict__ x) {
    int blk = blockIdx.x;
    int bg = blk >> 3, slice = blk & 7;
    const float4* p4 = (const float4*)(x + bg*GELEMS + slice*(GELEMS/8));
    float s = 0.f, sq = 0.f;
    for (int i = threadIdx.x; i < GELEMS/8/4; i += 256) {
        float4 v = p4[i];
        s  += v.x + v.y + v.z + v.w;
        sq += v.x*v.x + v.y*v.y + v.z*v.z + v.w*v.w;
    }
    __shared__ float ss[256], ssq[256];
    ss[threadIdx.x] = s; ssq[threadIdx.x] = sq;
    __syncthreads();
    for (int st = 128; st > 0; st >>= 1) {
        if (threadIdx.x < st) {
            ss[threadIdx.x]  += ss[threadIdx.x + st];
            ssq[threadIdx.x] += ssq[threadIdx.x + st];
        }
        __syncthreads();
    }
    if (threadIdx.x == 0) {
        g_gnpart[blk*2 + 0] = ss[0];
        g_gnpart[blk*2 + 1] = ssq[0];
    }
}

// ---------------- GroupNorm apply + transpose -> fp16 [b][p][c] ----------------
__global__ __launch_bounds__(256) void gn_apply_t(const float* __restrict__ x,
                                                  const float* __restrict__ gamma,
                                                  const float* __restrict__ beta) {
    __shared__ float tile[64][65];
    __shared__ float s_ga[64], s_be[64];
    int b = blockIdx.z;
    int p0 = blockIdx.x*64, c0 = blockIdx.y*64;
    int t = threadIdx.x;
    if (t < 64) {
        int c = c0 + t;
        int bg = b*GROUPS + (c >> 5);
        float s = 0.f, sq = 0.f;
#pragma unroll
        for (int k = 0; k < 8; k++) { s += g_gnpart[(bg*8+k)*2]; sq += g_gnpart[(bg*8+k)*2+1]; }
        float mean = s * (1.f/GELEMS);
        float var  = sq * (1.f/GELEMS) - mean*mean;
        float rstd = rsqrtf(var + EPS);
        float ga = gamma[c]*rstd;
        s_ga[t] = ga; s_be[t] = beta[c] - mean*ga;
    }
    __syncthreads();
    const float* X = x + (size_t)b*CH*NSP;
    int cr = t >> 4, p4 = (t & 15)*4;
#pragma unroll
    for (int i = 0; i < 4; i++) {
        int c = cr + i*16;
        float4 v = *(const float4*)&X[(size_t)(c0+c)*NSP + p0 + p4];
        float ga = s_ga[c], be = s_be[c];
        v.x = v.x*ga + be; v.y = v.y*ga + be; v.z = v.z*ga + be; v.w = v.w*ga + be;
        tile[c][p4+0] = v.x; tile[c][p4+1] = v.y; tile[c][p4+2] = v.z; tile[c][p4+3] = v.w;
    }
    __syncthreads();
    __half* O = g_xnt + (size_t)b*NSP*CH;
    int pr = t >> 4, c4 = (t & 15)*4;
#pragma unroll
    for (int i = 0; i < 4; i++) {
        int p = pr + i*16;
        __half2 lo = __floats2half2_rn(tile[c4+0][p], tile[c4+1][p]);
        __half2 hi = __floats2half2_rn(tile[c4+2][p], tile[c4+3][p]);
        uint2 pk; pk.x = *(uint32_t*)&lo; pk.y = *(uint32_t*)&hi;
        *(uint2*)&O[(size_t)(p0+p)*CH + c0 + c4] = pk;
    }
}

// ---------------- fp32 -> fp16 weight conversion (both weights, one launch) ----------------
__global__ void conv_f16_all(const float* __restrict__ wq, const float* __restrict__ wp) {
    int i = (blockIdx.x*256 + threadIdx.x) * 4;
    const float* src; __half* dst; int off;
    if (i < 3*CH*CH) { src = wq; dst = g_wq; off = i; }
    else             { src = wp; dst = g_wp; off = i - 3*CH*CH; }
    float4 v = *(const float4*)&src[off];
    __half2 lo = __floats2half2_rn(v.x, v.y);
    __half2 hi = __floats2half2_rn(v.z, v.w);
    uint2 pk; pk.x = *(uint32_t*)&lo; pk.y = *(uint32_t*)&hi;
    *(uint2*)&dst[off] = pk;
}

#define MMA_F16(d, a, b) \
    asm volatile("mma.sync.aligned.m16n8k16.row.col.f32.f16.f16.f32 " \
        "{%0,%1,%2,%3}, {%4,%5,%6,%7}, {%8,%9}, {%0,%1,%2,%3};" \
        : "+f"((d)[0]), "+f"((d)[1]), "+f"((d)[2]), "+f"((d)[3]) \
        : "r"((a)[0]), "r"((a)[1]), "r"((a)[2]), "r"((a)[3]), \
          "r"((b)[0]), "r"((b)[1]))

#define LDSM_X4(r0, r1, r2, r3, addr) \
    asm volatile("ldmatrix.sync.aligned.m8n8.x4.shared.b16 {%0,%1,%2,%3}, [%4];" \
        : "=r"(r0), "=r"(r1), "=r"(r2), "=r"(r3) : "r"(addr))

#define EX2_H2(dst, src) \
    asm("ex2.approx.f16x2 %0, %1;" : "=r"(dst) : "r"(src))

#define CPA16(so, gp) \
    asm volatile("cp.async.cg.shared.global [%0], [%1], 16;" :: "r"(so), "l"(gp))
#define CPA_COMMIT() asm volatile("cp.async.commit_group;" ::: "memory")
#define CPA_WAIT2()  asm volatile("cp.async.wait_group 2;" ::: "memory")
#define CPA_WAIT3()  asm volatile("cp.async.wait_group 3;" ::: "memory")

// ldmatrix per-lane byte offsets (stride in halfs = STR)
#define AOFF(l, STR) ((((l) & 15)*(STR) + (((l) >> 4) << 3)) * 2)
#define BOFF(l, STR) (((((l) & 7) + (((l) >> 4) << 3))*(STR) + ((((l) >> 3) & 1) << 3)) * 2)

// ================= fused flash attention =================
// grid (32 q-tiles, 4 batches), 256 threads. Q resident; 32 KV chunks of 128.
// Per chunk: 8 K-tiles (S) + 4 V-tiles (PV); 5-slot cp.async ring, depth-4 prefetch.
// No-max softmax with h2 ex2; O divided by rowsum l at the end.
#define FSTR 40
#define QCHH (128*FSTR)
#define PCHH (128*FSTR)
#define RSLOTH (256*FSTR)
#define NRING 5
#define FSMEM ((8*QCHH + 4*PCHH + NRING*RSLOTH)*2 + 512 + 16)

__global__ __launch_bounds__(256, 1) void flash_attn() {
    extern __shared__ __half smh[];
    __half* Qs   = smh;                      // 8 chunks x [128][40]
    __half* Ps   = smh + 8*QCHH;             // 4 chunks x [128][40]
    __half* Ring = Ps + 4*PCHH;              // NRING slots x [256][40]
    float*  sl   = (float*)(Ring + NRING*RSLOTH);

    int t = threadIdx.x;
    int lane = t & 31, wid = t >> 5;
    int g = lane >> 2, tg = lane & 3;
    int wm = wid >> 2, wn = wid & 3;          // 2 x 4
    int p0 = blockIdx.x * 128;
    long b = blockIdx.y;
    const __half* QK = g_qkvt + b*(long)NSP*512;
    const __half* VT = g_vt   + b*(long)CH*NSP;

    int lrow = t >> 2, lc = (t & 3) * 8;
    uint32_t qsu   = (uint32_t)__cvta_generic_to_shared(Qs);
    uint32_t psu   = (uint32_t)__cvta_generic_to_shared(Ps);
    uint32_t ringu = (uint32_t)__cvta_generic_to_shared(Ring);
    uint32_t aoff = AOFF(lane, FSTR);
    uint32_t boff = BOFF(lane, FSTR);

    // ---- resident Q load (8 chunks of 32 k) ----
#pragma unroll
    for (int c = 0; c < 8; c++)
#pragma unroll
        for (int i = 0; i < 2; i++) {
            int row = lrow + i*64;
            uint32_t so = qsu + (c*QCHH + row*FSTR + lc)*2;
            const __half* gp = QK + (long)(p0+row)*512 + c*32 + lc;
            CPA16(so, gp);
        }
    CPA_COMMIT();
    if (t < 128) sl[t] = 0.f;

    // tile issue: j<8 -> K tile (k-step j); j>=8 -> V tile (k-step j-8)
    auto issue = [&](int c, int j, int slot) {
        uint32_t sb = ringu + slot*RSLOTH*2;
        int kv0 = c*128;
        if (j < 8) {
#pragma unroll
            for (int i = 0; i < 2; i++) {
                int row = lrow + i*64;
                uint32_t so = sb + (row*FSTR + lc)*2;
                const __half* gp = QK + (long)(kv0+row)*512 + 256 + j*32 + lc;
                CPA16(so, gp);
            }
        } else {
#pragma unroll
            for (int i = 0; i < 4; i++) {
                int row = lrow + i*64;
                uint32_t so = sb + (row*FSTR + lc)*2;
                const __half* gp = VT + (long)row*NSP + kv0 + (j-8)*32 + lc;
                CPA16(so, gp);
            }
        }
    };

    float oacc[4][8][4];
#pragma unroll
    for (int mi = 0; mi < 4; mi++)
#pragma unroll
        for (int nj = 0; nj < 8; nj++)
#pragma unroll
            for (int r = 0; r < 4; r++) oacc[mi][nj][r] = 0.f;
    float sacc[4][4][4];
#pragma unroll
    for (int mi = 0; mi < 4; mi++)
#pragma unroll
        for (int nj = 0; nj < 4; nj++)
#pragma unroll
            for (int r = 0; r < 4; r++) sacc[mi][nj][r] = 0.f;

    const int NCH = NSP/128;       // 32 chunks
    const int T = NCH*12;
    const float ESL = 0.0625f * 1.44269504f;     // scale * log2(e)
    const __half2 hclamp = __float2half2_rn(11.0f);

    // prologue: depth-4 prefetch
    issue(0, 0, 0); CPA_COMMIT();
    issue(0, 1, 1); CPA_COMMIT();
    issue(0, 2, 2); CPA_COMMIT();
    issue(0, 3, 3); CPA_COMMIT();
    int nc = 0, njx = 4;

    for (int gt = 0; gt < T; gt++) {
        int j = gt % 12;
        int slot = gt % NRING;
        CPA_WAIT3();
        __syncthreads();
        if (gt + 4 < T) issue(nc, njx, (gt+4) % NRING);
        CPA_COMMIT();
        if (++njx == 12) { njx = 0; nc++; }

        if (j < 8) {
            // ---- S step ----
            uint32_t Abase = qsu + (j*QCHH + (wm*64)*FSTR)*2 + aoff;
            uint32_t Bbase = ringu + (slot*RSLOTH + (wn*32)*FSTR)*2 + boff;
#pragma unroll
            for (int kk = 0; kk < 32; kk += 16) {
                uint32_t af[4][4];
#pragma unroll
                for (int mi = 0; mi < 4; mi++)
                    LDSM_X4(af[mi][0], af[mi][1], af[mi][2], af[mi][3],
                            Abase + (mi*16*FSTR + kk)*2);
#pragma unroll
                for (int njp = 0; njp < 2; njp++) {
                    uint32_t bfa[2], bfb[2];
                    LDSM_X4(bfa[0], bfa[1], bfb[0], bfb[1],
                            Bbase + (njp*16*FSTR + kk)*2);
#pragma unroll
                    for (int mi = 0; mi < 4; mi++) {
                        MMA_F16(sacc[mi][njp*2+0], af[mi], bfa);
                        MMA_F16(sacc[mi][njp*2+1], af[mi], bfb);
                    }
                }
            }
            if (j == 7) {
                // ---- exp (h2 ex2) + P->SMEM + rowsum; reset sacc ----
                __half* Pb = Ps + wn*PCHH;
#pragma unroll
                for (int mi = 0; mi < 4; mi++) {
                    int r0l = wm*64 + mi*16 + g;
                    int r1l = r0l + 8;
                    __half2 rsh0 = __float2half2_rn(0.f);
                    __half2 rsh1 = __float2half2_rn(0.f);
#pragma unroll
                    for (int nj = 0; nj < 4; nj++) {
                        int colb = nj*8 + tg*2;
                        float y00 = sacc[mi][nj][0]*ESL, y01 = sacc[mi][nj][1]*ESL;
                        float y10 = sacc[mi][nj][2]*ESL, y11 = sacc[mi][nj][3]*ESL;
                        __half2 h0 = __hmin2(__floats2half2_rn(y00, y01), hclamp);
                        __half2 h1 = __hmin2(__floats2half2_rn(y10, y11), hclamp);
                        uint32_t p0r, p1r;
                        EX2_H2(p0r, *(uint32_t*)&h0);
                        EX2_H2(p1r, *(uint32_t*)&h1);
                        __half2 e0 = *(__half2*)&p0r, e1 = *(__half2*)&p1r;
                        *(__half2*)(Pb + r0l*FSTR + colb) = e0;
                        *(__half2*)(Pb + r1l*FSTR + colb) = e1;
                        rsh0 = __hadd2(rsh0, e0);
                        rsh1 = __hadd2(rsh1, e1);
                        sacc[mi][nj][0] = 0.f; sacc[mi][nj][1] = 0.f;
                        sacc[mi][nj][2] = 0.f; sacc[mi][nj][3] = 0.f;
                    }
                    float rs0 = __low2float(rsh0) + __high2float(rsh0);
                    float rs1 = __low2float(rsh1) + __high2float(rsh1);
                    rs0 += __shfl_xor_sync(~0u, rs0, 1);
                    rs0 += __shfl_xor_sync(~0u, rs0, 2);
                    rs1 += __shfl_xor_sync(~0u, rs1, 1);
                    rs1 += __shfl_xor_sync(~0u, rs1, 2);
                    if (tg == 0) {
                        atomicAdd(&sl[r0l], rs0);
                        atomicAdd(&sl[r1l], rs1);
                    }
                }
            }
        } else {
            // ---- PV step ----
            int kt = j - 8;
            uint32_t Abase = psu + (kt*PCHH + (wm*64)*FSTR)*2 + aoff;
            uint32_t Bbase = ringu + (slot*RSLOTH + (wn*64)*FSTR)*2 + boff;
#pragma unroll
            for (int kk = 0; kk < 32; kk += 16) {
                uint32_t af[4][4];
#pragma unroll
                for (int mi = 0; mi < 4; mi++)
                    LDSM_X4(af[mi][0], af[mi][1], af[mi][2], af[mi][3],
                            Abase + (mi*16*FSTR + kk)*2);
#pragma unroll
                for (int njp = 0; njp < 4; njp++) {
                    uint32_t bfa[2], bfb[2];
                    LDSM_X4(bfa[0], bfa[1], bfb[0], bfb[1],
                            Bbase + (njp*16*FSTR + kk)*2);
#pragma unroll
                    for (int mi = 0; mi < 4; mi++) {
                        MMA_F16(oacc[mi][njp*2+0], af[mi], bfa);
                        MMA_F16(oacc[mi][njp*2+1], af[mi], bfb);
                    }
                }
            }
        }
    }

    __syncthreads();   // all rowsum atomics done
    __half* O = g_attn + b*(long)NSP*CH;
#pragma unroll
    for (int mi = 0; mi < 4; mi++) {
        int r0l = wm*64 + mi*16 + g;
        int r1l = r0l + 8;
        float inv0 = 1.0f / sl[r0l];
        float inv1 = 1.0f / sl[r1l];
#pragma unroll
        for (int nj = 0; nj < 8; nj++) {
            int ch = wn*64 + nj*8 + tg*2;
            __half2 h0 = __floats2half2_rn(oacc[mi][nj][0]*inv0, oacc[mi][nj][1]*inv0);
            __half2 h1 = __floats2half2_rn(oacc[mi][nj][2]*inv1, oacc[mi][nj][3]*inv1);
            *(__half2*)&O[(long)(p0 + r0l)*CH + ch] = h0;
            *(__half2*)&O[(long)(p0 + r1l)*CH + ch] = h1;
        }
    }
}

// ================= fp16 GEMM =================
// EPI: 0 = +bias[n], fp16 out   (QK)
//      1 = +bias[m], fp16 out   (V-direct)
//      3 = +bias[m] + res[m][n], fp32 out (proj)
#define BM 128
#define BN 256
#define BK 32
#define BTS 40
#define ATILB (128*BTS)
#define BTILB (256*BTS)
#define NSTG 4
#define SMEMSZ (NSTG*(ATILB+BTILB)*2)    // 122880 B

template<int EPI>
__global__ __launch_bounds__(256, 1) void mm_f16(
    const __half* __restrict__ Ag, int lda, long sAb,
    const __half* __restrict__ Bg, int ldb, long sBb,
    void* __restrict__ Cg, int ldc, long sCb,
    const float* __restrict__ bias,
    const float* __restrict__ resg, long sRb,
    int K)
{
    extern __shared__ __half smh2[];
    __half* As[NSTG] = { smh2, smh2 + ATILB, smh2 + 2*ATILB, smh2 + 3*ATILB };
    __half* Bs[NSTG] = { smh2 + 4*ATILB,             smh2 + 4*ATILB + BTILB,
                         smh2 + 4*ATILB + 2*BTILB,   smh2 + 4*ATILB + 3*BTILB };

    int t = threadIdx.x;
    int wid = t >> 5, lane = t & 31;
    int g = lane >> 2, tg = lane & 3;
    int wm = wid >> 2, wn = wid & 3;
    int n0 = blockIdx.x * BN, m0 = blockIdx.y * BM;
    long b = blockIdx.z;
    const __half* A = Ag + b*sAb;
    const __half* B = Bg + b*sBb;
    uint32_t aoff = AOFF(lane, BTS);
    uint32_t boff = BOFF(lane, BTS);

    int lrow = t >> 2, lc = (t & 3) * 8;
    auto loadAB = [&](int buf, int k0) {
        uint32_t sa = (uint32_t)__cvta_generic_to_shared(As[buf]);
        uint32_t sb = (uint32_t)__cvta_generic_to_shared(Bs[buf]);
#pragma unroll
        for (int i = 0; i < 2; i++) {
            int row = lrow + i*64;
            uint32_t so = sa + (row*BTS + lc) * 2;
            const __half* gp = A + (long)(m0+row)*lda + k0 + lc;
            CPA16(so, gp);
        }
#pragma unroll
        for (int i = 0; i < 4; i++) {
            int row = lrow + i*64;
            uint32_t so = sb + (row*BTS + lc) * 2;
            const __half* gp = B + (long)(n0+row)*ldb + k0 + lc;
            CPA16(so, gp);
        }
    };

    float acc[4][8][4];
#pragma unroll
    for (int mi = 0; mi < 4; mi++)
#pragma unroll
        for (int nj = 0; nj < 8; nj++)
#pragma unroll
            for (int r = 0; r < 4; r++) acc[mi][nj][r] = 0.f;

    const int NK = K / BK;
    loadAB(0, 0);      CPA_COMMIT();
    loadAB(1, BK);     CPA_COMMIT();
    loadAB(2, 2*BK);   CPA_COMMIT();

    int cur = 0;
    for (int kt = 0; kt < NK; kt++) {
        CPA_WAIT2();
        __syncthreads();
        if (kt + 3 < NK) loadAB((kt + 3) % NSTG, (kt+3)*BK);
        CPA_COMMIT();

        uint32_t Abase = (uint32_t)__cvta_generic_to_shared(As[cur]) + ((wm*64)*BTS)*2 + aoff;
        uint32_t Bbase = (uint32_t)__cvta_generic_to_shared(Bs[cur]) + ((wn*64)*BTS)*2 + boff;
#pragma unroll
        for (int kk = 0; kk < BK; kk += 16) {
            uint32_t af[4][4];
#pragma unroll
            for (int mi = 0; mi < 4; mi++)
                LDSM_X4(af[mi][0], af[mi][1], af[mi][2], af[mi][3],
                        Abase + (mi*16*BTS + kk)*2);
#pragma unroll
            for (int njp = 0; njp < 4; njp++) {
                uint32_t bfa[2], bfb[2];
                LDSM_X4(bfa[0], bfa[1], bfb[0], bfb[1],
                        Bbase + (njp*16*BTS + kk)*2);
#pragma unroll
                for (int mi = 0; mi < 4; mi++) {
                    MMA_F16(acc[mi][njp*2+0], af[mi], bfa);
                    MMA_F16(acc[mi][njp*2+1], af[mi], bfb);
                }
            }
        }
        cur = (cur + 1 == NSTG) ? 0 : cur + 1;
    }

    int mb = m0 + wm*64;
    int nb = n0 + wn*64;
    float* Cf = (float*)Cg;
    __half* Ch = (__half*)Cg;
#pragma unroll
    for (int mi = 0; mi < 4; mi++) {
        int r0 = mb + mi*16 + g;
        int r1 = r0 + 8;
        float add0 = 0.f, add1 = 0.f;
        if (EPI == 1 || EPI == 3) { add0 = bias[r0]; add1 = bias[r1]; }
#pragma unroll
        for (int nj = 0; nj < 8; nj++) {
            int col = nb + nj*8 + tg*2;
            float2 v0 = make_float2(acc[mi][nj][0], acc[mi][nj][1]);
            float2 v1 = make_float2(acc[mi][nj][2], acc[mi][nj][3]);
            long o0 = (long)r0*ldc + col + b*sCb;
            long o1 = (long)r1*ldc + col + b*sCb;
            if (EPI == 0) {
                float2 bv = *(const float2*)&bias[col];
                v0.x += bv.x; v0.y += bv.y; v1.x += bv.x; v1.y += bv.y;
                *(__half2*)&Ch[o0] = __floats2half2_rn(v0.x, v0.y);
                *(__half2*)&Ch[o1] = __floats2half2_rn(v1.x, v1.y);
            }
            if (EPI == 1) {
                v0.x += add0; v0.y += add0; v1.x += add1; v1.y += add1;
                *(__half2*)&Ch[o0] = __floats2half2_rn(v0.x, v0.y);
                *(__half2*)&Ch[o1] = __floats2half2_rn(v1.x, v1.y);
            }
            if (EPI == 3) {
                const float* R = resg + b*sRb;
                float2 x0 = *(const float2*)&R[(long)r0*ldc + col];
                float2 x1 = *(const float2*)&R[(long)r1*ldc + col];
                v0.x += add0 + x0.x; v0.y += add0 + x0.y;
                v1.x += add1 + x1.x; v1.y += add1 + x1.y;
                *(float2*)&Cf[o0] = v0;
                *(float2*)&Cf[o1] = v1;
            }
        }
    }
}

// ---------------- launch ----------------
extern "C" void kernel_launch(void* const* d_in, const int* in_sizes, int n_in,
                              void* d_out, int out_size) {
    const float* x      = (const float*)d_in[0];
    const float* gamma  = (const float*)d_in[1];
    const float* beta   = (const float*)d_in[2];
    const float* w_qkv  = (const float*)d_in[3];
    const float* b_qkv  = (const float*)d_in[4];
    const float* w_proj = (const float*)d_in[5];
    const float* b_proj = (const float*)d_in[6];
    float* out = (float*)d_out;

    __half *p_xnt, *p_qkvt, *p_vt, *p_attn, *p_wq, *p_wp;
    cudaGetSymbolAddress((void**)&p_xnt,  g_xnt);
    cudaGetSymbolAddress((void**)&p_qkvt, g_qkvt);
    cudaGetSymbolAddress((void**)&p_vt,   g_vt);
    cudaGetSymbolAddress((void**)&p_attn, g_attn);
    cudaGetSymbolAddress((void**)&p_wq,   g_wq);
    cudaGetSymbolAddress((void**)&p_wp,   g_wp);

    cudaFuncSetAttribute(mm_f16<0>, cudaFuncAttributeMaxDynamicSharedMemorySize, SMEMSZ);
    cudaFuncSetAttribute(mm_f16<1>, cudaFuncAttributeMaxDynamicSharedMemorySize, SMEMSZ);
    cudaFuncSetAttribute(mm_f16<3>, cudaFuncAttributeMaxDynamicSharedMemorySize, SMEMSZ);
    cudaFuncSetAttribute(flash_attn, cudaFuncAttributeMaxDynamicSharedMemorySize, FSMEM);

    // 1-2. GroupNorm (apply fused with transpose, fp16 out)
    gn_partial<<<BATCH*GROUPS*8, 256>>>(x);
    gn_apply_t<<<dim3(NSP/64, CH/64, BATCH), 256>>>(x, gamma, beta);

    // weights -> fp16 (one launch)
    conv_f16_all<<<4*CH*CH/4/256, 256>>>(w_qkv, w_proj);

    // 3. QK: D[p][o] = xnt[p][c] * w_qk[o][c]^T + b[o], o in [0,512)  (fp16 out)
    mm_f16<0><<<dim3(2*CH/BN, NSP/BM, BATCH), 256, SMEMSZ>>>(
        p_xnt, CH, (long)NSP*CH,
        p_wq, CH, 0,
        p_qkvt, 2*CH, (long)NSP*2*CH,
        b_qkv, nullptr, 0, CH);

    // 4. V direct-transposed: Vt[c][p] = w_v[c][:] . xnt[p][:] + b_v[c]  (fp16 out)
    mm_f16<1><<<dim3(NSP/BN, CH/BM, BATCH), 256, SMEMSZ>>>(
        p_wq + 512*CH, CH, 0,
        p_xnt, CH, (long)NSP*CH,
        p_vt, NSP, (long)CH*NSP,
        b_qkv + 512, nullptr, 0, CH);

    // 5. fused attention: S -> exp -> PV, P in SMEM only
    flash_attn<<<dim3(NSP/128, BATCH), 256, FSMEM>>>();

    // 6. out[co][p] = w_proj[co][c] * attn[p][c]^T + b_proj[co] + x   (fp32 out)
    mm_f16<3><<<dim3(NSP/BN, CH/BM, BATCH), 256, SMEMSZ>>>(
        p_wp, CH, 0,
        p_attn, CH, (long)NSP*CH,
        out, NSP, (long)CH*NSP,
        b_proj, x, (long)CH*NSP, CH);
}